// round 1
// baseline (speedup 1.0000x reference)
#include <cuda_runtime.h>
#include <math.h>

// Problem constants
#define NB     8
#define LSEQ   2048
#define BL     16384          // NB*LSEQ
#define DLEN   512
#define DM     256
#define NPROJ  1024           // Q|K|V|Add concatenated
#define MRF    256
#define TWOM   512
#define NCLASS 64
#define FTOT   (LSEQ*DM)      // 524288 flattened features per batch

#define TWO_PI 6.28318530717958647692f

// ---------------- device scratch (allocation-free rule: static globals) ----
__device__ float g_qkva[BL * NPROJ];      // 64 MB : [row, 1024] = Q|K|V|Add
__device__ float g_scale_q[BL];
__device__ float g_scale_k[BL];
__device__ float g_qp[BL * TWOM];         // 32 MB
__device__ float g_kp[BL * TWOM];         // 32 MB
__device__ float g_ksum[NB * TWOM];
__device__ float g_kv[NB * TWOM * DM];    // 4 MB
__device__ float g_denom[BL];
__device__ float g_out[BL * DM];          // 16 MB (== [b, FTOT] flat)

// ============================================================================
// Kernel 1: C[BL,1024] = X[BL,512] @ Wcat[1024,512]^T   (NT, both K-contig)
// 128x128 tile, BK=16, 8x8 per thread, 256 threads.
// ============================================================================
__global__ void __launch_bounds__(256) k_proj(const float* __restrict__ X,
                                              const float* __restrict__ Wq,
                                              const float* __restrict__ Wk,
                                              const float* __restrict__ Wv,
                                              const float* __restrict__ Wa)
{
    const int bn = blockIdx.x;            // 0..7   (n tile)
    const int bm = blockIdx.y;            // 0..127 (m tile)
    const int which = bn >> 1;
    const float* W = (which == 0) ? Wq : (which == 1) ? Wk : (which == 2) ? Wv : Wa;
    const float* Wbase = W + (size_t)(bn & 1) * 128 * DLEN;
    const float* Abase = X + (size_t)bm * 128 * DLEN;

    __shared__ float As[16][132];
    __shared__ float Bs[16][132];

    const int tid = threadIdx.x;
    const int tx = tid & 15, ty = tid >> 4;

    float acc[8][8] = {};

    for (int k0 = 0; k0 < DLEN; k0 += 16) {
#pragma unroll
        for (int i = 0; i < 2; i++) {
            int v = tid + i * 256;        // 0..511 float4 slots
            int row = v >> 2, kq = v & 3;
            float4 t = *(const float4*)(Abase + (size_t)row * DLEN + k0 + kq * 4);
            As[kq*4+0][row] = t.x; As[kq*4+1][row] = t.y;
            As[kq*4+2][row] = t.z; As[kq*4+3][row] = t.w;
        }
#pragma unroll
        for (int i = 0; i < 2; i++) {
            int v = tid + i * 256;
            int row = v >> 2, kq = v & 3;
            float4 t = *(const float4*)(Wbase + (size_t)row * DLEN + k0 + kq * 4);
            Bs[kq*4+0][row] = t.x; Bs[kq*4+1][row] = t.y;
            Bs[kq*4+2][row] = t.z; Bs[kq*4+3][row] = t.w;
        }
        __syncthreads();
#pragma unroll
        for (int k = 0; k < 16; k++) {
            float a[8], b[8];
#pragma unroll
            for (int i = 0; i < 8; i++) a[i] = As[k][ty * 8 + i];
#pragma unroll
            for (int j = 0; j < 8; j++) b[j] = Bs[k][tx * 8 + j];
#pragma unroll
            for (int i = 0; i < 8; i++)
#pragma unroll
                for (int j = 0; j < 8; j++)
                    acc[i][j] = fmaf(a[i], b[j], acc[i][j]);
        }
        __syncthreads();
    }

    float* Cbase = g_qkva + (size_t)(bm * 128) * NPROJ + bn * 128;
#pragma unroll
    for (int i = 0; i < 8; i++) {
        float* crow = Cbase + (size_t)(ty * 8 + i) * NPROJ + tx * 8;
        *(float4*)(crow)     = make_float4(acc[i][0], acc[i][1], acc[i][2], acc[i][3]);
        *(float4*)(crow + 4) = make_float4(acc[i][4], acc[i][5], acc[i][6], acc[i][7]);
    }
}

// ============================================================================
// Kernel 2: per-row scale = exp(0.5*||q||^2) / sqrt(M),  for Q and K halves.
// One warp per row.
// ============================================================================
__global__ void k_rowscale()
{
    int warp = (blockIdx.x * blockDim.x + threadIdx.x) >> 5;
    int lane = threadIdx.x & 31;
    int isK = blockIdx.y;
    if (warp >= BL) return;
    const float* row = g_qkva + (size_t)warp * NPROJ + (isK ? DM : 0);
    float s = 0.f;
#pragma unroll
    for (int i = lane; i < DM; i += 32) { float v = row[i]; s = fmaf(v, v, s); }
#pragma unroll
    for (int o = 16; o; o >>= 1) s += __shfl_xor_sync(0xFFFFFFFFu, s, o);
    if (lane == 0) {
        float sc = expf(0.5f * s) * 0.0625f;   // 1/sqrt(256) = 1/16
        (isK ? g_scale_k : g_scale_q)[warp] = sc;
    }
}

// ============================================================================
// Kernel 3: phi.  proj = (Q or K)[BL,256] @ rf[256,256]^T  (NT, K=256),
// epilogue writes sin/cos * scale to qp/kp [BL, 512].
// ============================================================================
__global__ void __launch_bounds__(256) k_phi(const float* __restrict__ rf)
{
    const int bn = blockIdx.x;            // 0..1 feature tile
    const int bm = blockIdx.y;            // 0..127 row tile
    const int isK = blockIdx.z;
    const float* Abase = g_qkva + (size_t)bm * 128 * NPROJ + (isK ? DM : 0);
    const float* Bbase = rf + (size_t)bn * 128 * MRF;

    __shared__ float As[16][132];
    __shared__ float Bs[16][132];

    const int tid = threadIdx.x;
    const int tx = tid & 15, ty = tid >> 4;

    float acc[8][8] = {};

    for (int k0 = 0; k0 < MRF; k0 += 16) {
#pragma unroll
        for (int i = 0; i < 2; i++) {
            int v = tid + i * 256;
            int row = v >> 2, kq = v & 3;
            float4 t = *(const float4*)(Abase + (size_t)row * NPROJ + k0 + kq * 4);
            As[kq*4+0][row] = t.x; As[kq*4+1][row] = t.y;
            As[kq*4+2][row] = t.z; As[kq*4+3][row] = t.w;
        }
#pragma unroll
        for (int i = 0; i < 2; i++) {
            int v = tid + i * 256;
            int row = v >> 2, kq = v & 3;
            float4 t = *(const float4*)(Bbase + (size_t)row * MRF + k0 + kq * 4);
            Bs[kq*4+0][row] = t.x; Bs[kq*4+1][row] = t.y;
            Bs[kq*4+2][row] = t.z; Bs[kq*4+3][row] = t.w;
        }
        __syncthreads();
#pragma unroll
        for (int k = 0; k < 16; k++) {
            float a[8], b[8];
#pragma unroll
            for (int i = 0; i < 8; i++) a[i] = As[k][ty * 8 + i];
#pragma unroll
            for (int j = 0; j < 8; j++) b[j] = Bs[k][tx * 8 + j];
#pragma unroll
            for (int i = 0; i < 8; i++)
#pragma unroll
                for (int j = 0; j < 8; j++)
                    acc[i][j] = fmaf(a[i], b[j], acc[i][j]);
        }
        __syncthreads();
    }

    float* OUT = isK ? g_kp : g_qp;
    const float* SC = isK ? g_scale_k : g_scale_q;
    const int row0 = bm * 128;
    const int nbase = bn * 128 + tx * 8;
#pragma unroll
    for (int i = 0; i < 8; i++) {
        int r = row0 + ty * 8 + i;
        float sc = SC[r];
        float* orow = OUT + (size_t)r * TWOM + nbase;
#pragma unroll
        for (int j = 0; j < 8; j++) {
            float s, c;
            sincosf(TWO_PI * acc[i][j], &s, &c);
            orow[j]      = s * sc;     // sin half  (cols [0,256))
            orow[j + DM] = c * sc;     // cos half  (cols [256,512))
        }
    }
}

// ============================================================================
// Kernel 4: ksum[b, m] = sum_l kp[b, l, m].   Block: (m-chunk of 64, b).
// 256 threads = 64 m-lanes x 4 L-groups.
// ============================================================================
__global__ void k_ksum()
{
    const int b = blockIdx.y;
    const int mi = threadIdx.x & 63;
    const int m = blockIdx.x * 64 + mi;
    const int lg = threadIdx.x >> 6;
    const float* base = g_kp + ((size_t)b * LSEQ + lg) * TWOM + m;
    float s = 0.f;
    for (int l = 0; l < LSEQ; l += 4) s += base[(size_t)l * TWOM];
    __shared__ float red[4][64];
    red[lg][mi] = s;
    __syncthreads();
    if (lg == 0)
        g_ksum[b * TWOM + m] = red[0][mi] + red[1][mi] + red[2][mi] + red[3][mi];
}

// ============================================================================
// Kernel 5: kv[b, m, d] = sum_l kp[b,l,m] * v[b,l,d]   (TN, contraction = l)
// 64x64 tile, BK=16, 4x4 per thread, 256 threads.
// ============================================================================
__global__ void __launch_bounds__(256) k_kv()
{
    const int d0 = blockIdx.x * 64;
    const int m0 = blockIdx.y * 64;
    const int b  = blockIdx.z;

    const float* Kbase = g_kp + (size_t)b * LSEQ * TWOM;        // [l, 512]
    const float* Vbase = g_qkva + (size_t)b * LSEQ * NPROJ + 2 * DM;  // V cols

    __shared__ float As[16][68];
    __shared__ float Bs[16][68];

    const int tid = threadIdx.x;
    const int tx = tid & 15, ty = tid >> 4;
    const int lt  = tid >> 4;          // 0..15 load row
    const int mi4 = (tid & 15) * 4;    // 0..60 load col

    float acc[4][4] = {};

    for (int l0 = 0; l0 < LSEQ; l0 += 16) {
        {
            float4 t = *(const float4*)(Kbase + (size_t)(l0 + lt) * TWOM + m0 + mi4);
            As[lt][mi4] = t.x; As[lt][mi4+1] = t.y; As[lt][mi4+2] = t.z; As[lt][mi4+3] = t.w;
            float4 u = *(const float4*)(Vbase + (size_t)(l0 + lt) * NPROJ + d0 + mi4);
            Bs[lt][mi4] = u.x; Bs[lt][mi4+1] = u.y; Bs[lt][mi4+2] = u.z; Bs[lt][mi4+3] = u.w;
        }
        __syncthreads();
#pragma unroll
        for (int k = 0; k < 16; k++) {
            float a[4], bb[4];
#pragma unroll
            for (int i = 0; i < 4; i++) a[i] = As[k][ty * 4 + i];
#pragma unroll
            for (int j = 0; j < 4; j++) bb[j] = Bs[k][tx * 4 + j];
#pragma unroll
            for (int i = 0; i < 4; i++)
#pragma unroll
                for (int j = 0; j < 4; j++)
                    acc[i][j] = fmaf(a[i], bb[j], acc[i][j]);
        }
        __syncthreads();
    }

#pragma unroll
    for (int i = 0; i < 4; i++) {
        float* p = g_kv + ((size_t)b * TWOM + m0 + ty * 4 + i) * DM + d0 + tx * 4;
        *(float4*)p = make_float4(acc[i][0], acc[i][1], acc[i][2], acc[i][3]);
    }
}

// ============================================================================
// Kernel 6: denom[row] = sum_m qp[row,m] * ksum[b,m].  One warp per row.
// ============================================================================
__global__ void k_denom()
{
    int warp = (blockIdx.x * blockDim.x + threadIdx.x) >> 5;
    int lane = threadIdx.x & 31;
    if (warp >= BL) return;
    const float* q  = g_qp  + (size_t)warp * TWOM;
    const float* ks = g_ksum + (size_t)(warp >> 11) * TWOM;
    float s = 0.f;
#pragma unroll
    for (int i = lane; i < TWOM; i += 32) s = fmaf(q[i], ks[i], s);
#pragma unroll
    for (int o = 16; o; o >>= 1) s += __shfl_xor_sync(0xFFFFFFFFu, s, o);
    if (lane == 0) g_denom[warp] = s;
}

// ============================================================================
// Kernel 7: num[b,l,d] = sum_m qp[b,l,m] * kv[b,m,d]  (NN), fused epilogue:
//   out = num/denom + addproj + b_add   -> g_out
// 128x128 tile, BK=16, 8x8 per thread.
// ============================================================================
__global__ void __launch_bounds__(256) k_num(const float* __restrict__ b_add)
{
    const int bn = blockIdx.x;            // 0..1 d tile
    const int bm = blockIdx.y;            // 0..15 l tile
    const int b  = blockIdx.z;

    const float* Abase = g_qp + ((size_t)(b * LSEQ + bm * 128)) * TWOM;  // [l,512]
    const float* Bbase = g_kv + (size_t)b * TWOM * DM + bn * 128;        // [m,256]

    __shared__ float As[16][132];
    __shared__ float Bs[16][132];

    const int tid = threadIdx.x;
    const int tx = tid & 15, ty = tid >> 4;

    float acc[8][8] = {};

    for (int k0 = 0; k0 < TWOM; k0 += 16) {
#pragma unroll
        for (int i = 0; i < 2; i++) {
            int v = tid + i * 256;
            int row = v >> 2, kq = v & 3;       // A: transpose load
            float4 t = *(const float4*)(Abase + (size_t)row * TWOM + k0 + kq * 4);
            As[kq*4+0][row] = t.x; As[kq*4+1][row] = t.y;
            As[kq*4+2][row] = t.z; As[kq*4+3][row] = t.w;
        }
#pragma unroll
        for (int i = 0; i < 2; i++) {
            int v = tid + i * 256;
            int kt = v >> 5, d4 = (v & 31) * 4;  // B: direct load
            float4 t = *(const float4*)(Bbase + (size_t)(k0 + kt) * DM + d4);
            Bs[kt][d4] = t.x; Bs[kt][d4+1] = t.y; Bs[kt][d4+2] = t.z; Bs[kt][d4+3] = t.w;
        }
        __syncthreads();
#pragma unroll
        for (int k = 0; k < 16; k++) {
            float a[8], bb[8];
#pragma unroll
            for (int i = 0; i < 8; i++) a[i] = As[k][ty * 8 + i];
#pragma unroll
            for (int j = 0; j < 8; j++) bb[j] = Bs[k][tx * 8 + j];
#pragma unroll
            for (int i = 0; i < 8; i++)
#pragma unroll
                for (int j = 0; j < 8; j++)
                    acc[i][j] = fmaf(a[i], bb[j], acc[i][j]);
        }
        __syncthreads();
    }

    const int dbase = bn * 128 + tx * 8;
#pragma unroll
    for (int i = 0; i < 8; i++) {
        int r = b * LSEQ + bm * 128 + ty * 8 + i;     // global row
        float den = g_denom[r];
        const float* addp = g_qkva + (size_t)r * NPROJ + 3 * DM + dbase;
        float* orow = g_out + (size_t)r * DM + dbase;
#pragma unroll
        for (int j = 0; j < 8; j++) {
            orow[j] = acc[i][j] / den + addp[j] + b_add[dbase + j];
        }
    }
}

// ============================================================================
// Kernel 8a: init d_out with b_final (output poisoned by harness).
// ============================================================================
__global__ void k_init_out(float* __restrict__ out, const float* __restrict__ bf)
{
    int i = threadIdx.x;                 // 512 threads
    out[i] = bf[i & 63];
}

// ============================================================================
// Kernel 8b: result[b,c] += sum_f out[b,f] * Wf[c,f]   (split-K, atomics)
// Each block: 1024-wide f chunk, staged through smem in 128-f tiles.
// thread t owns (c = t&63, b in {t>>6, (t>>6)+4}).
// ============================================================================
__global__ void __launch_bounds__(256) k_final(const float* __restrict__ Wf,
                                               float* __restrict__ out)
{
    __shared__ float Ws[64][130];
    __shared__ float Os[8][132];

    const int tid = threadIdx.x;
    const int c  = tid & 63;
    const int bb = tid >> 6;             // 0..3
    float acc0 = 0.f, acc1 = 0.f;
    const int f0 = blockIdx.x * 1024;

    for (int t = 0; t < 1024; t += 128) {
        const int fbase = f0 + t;
#pragma unroll
        for (int i = 0; i < 8; i++) {    // Ws: 2048 float4 / 256 thr
            int v = tid + i * 256;
            int cc = v >> 5, f4 = (v & 31) * 4;
            float4 w = *(const float4*)(Wf + (size_t)cc * FTOT + fbase + f4);
            Ws[cc][f4] = w.x; Ws[cc][f4+1] = w.y; Ws[cc][f4+2] = w.z; Ws[cc][f4+3] = w.w;
        }
        {                                // Os: 256 float4 / 256 thr
            int v = tid;
            int bo = v >> 5, f4 = (v & 31) * 4;
            float4 o = *(const float4*)(g_out + (size_t)bo * FTOT + fbase + f4);
            Os[bo][f4] = o.x; Os[bo][f4+1] = o.y; Os[bo][f4+2] = o.z; Os[bo][f4+3] = o.w;
        }
        __syncthreads();
#pragma unroll 8
        for (int fi = 0; fi < 128; fi++) {
            float w = Ws[c][fi];
            acc0 = fmaf(Os[bb][fi],     w, acc0);
            acc1 = fmaf(Os[bb + 4][fi], w, acc1);
        }
        __syncthreads();
    }
    atomicAdd(&out[bb * NCLASS + c],       acc0);
    atomicAdd(&out[(bb + 4) * NCLASS + c], acc1);
}

// ============================================================================
extern "C" void kernel_launch(void* const* d_in, const int* in_sizes, int n_in,
                              void* d_out, int out_size)
{
    const float* X  = (const float*)d_in[0];
    // d_in[1..6]: unused scalars (fai_x, fai_x_prime, w_1, b_1, w_2, b_2)
    const float* Wq = (const float*)d_in[7];
    const float* Wk = (const float*)d_in[8];
    const float* Wv = (const float*)d_in[9];
    const float* Wa = (const float*)d_in[10];
    const float* bA = (const float*)d_in[11];
    const float* Wf = (const float*)d_in[12];
    const float* bF = (const float*)d_in[13];
    const float* rf = (const float*)d_in[14];
    float* out = (float*)d_out;

    k_proj    <<<dim3(8, 128),    256>>>(X, Wq, Wk, Wv, Wa);
    k_rowscale<<<dim3(2048, 2),   256>>>();
    k_phi     <<<dim3(2, 128, 2), 256>>>(rf);
    k_ksum    <<<dim3(8, 8),      256>>>();
    k_kv      <<<dim3(4, 8, 8),   256>>>();
    k_denom   <<<2048,            256>>>();
    k_num     <<<dim3(2, 16, 8),  256>>>(bA);
    k_init_out<<<1, 512>>>(out, bF);
    k_final   <<<512, 256>>>(Wf, out);
}

// round 3
// speedup vs baseline: 1.3036x; 1.3036x over previous
#include <cuda_runtime.h>
#include <cuda_bf16.h>
#include <math.h>
#include <cstdint>

// Problem constants
#define NB     8
#define LSEQ   2048
#define BL     16384          // NB*LSEQ
#define DLEN   512
#define DM     256
#define NPROJ  1024           // Q|K|V|Add concatenated
#define MRF    256
#define TWOM   512
#define NCLASS 64
#define FTOT   (LSEQ*DM)      // 524288 flattened features per batch

#define TWO_PI 6.28318530717958647692f

// ---------------- device scratch (allocation-free rule: static globals) ----
__device__ float g_qkva[BL * NPROJ];      // 64 MB : [row, 1024] = Q|K|V|Add
__device__ float g_scale_q[BL];
__device__ float g_scale_k[BL];
__device__ float g_qp[BL * TWOM];         // 32 MB
__device__ float g_kp[BL * TWOM];         // 32 MB
__device__ float g_ksum[NB * TWOM];
__device__ float g_kv[NB * TWOM * DM];    // 4 MB
__device__ float g_denom[BL];
__device__ float g_out[BL * DM];          // 16 MB (== [b, FTOT] flat)

// ============================================================================
// mma.sync helpers (baseline PTX — valid at compute_100, no 'a' features)
// ============================================================================
__device__ __forceinline__ uint32_t smem_u32(const void* p) {
    uint32_t a;
    asm("{ .reg .u64 t; cvta.to.shared.u64 t, %1; cvt.u32.u64 %0, t; }" : "=r"(a) : "l"(p));
    return a;
}

__device__ __forceinline__ void ldmx4(uint32_t r[4], const void* p) {
    uint32_t a = smem_u32(p);
    asm volatile("ldmatrix.sync.aligned.m8n8.x4.shared.b16 {%0,%1,%2,%3}, [%4];"
                 : "=r"(r[0]), "=r"(r[1]), "=r"(r[2]), "=r"(r[3]) : "r"(a));
}

__device__ __forceinline__ void mma16816(float d[4], const uint32_t a[4],
                                         uint32_t b0, uint32_t b1) {
    asm volatile(
        "mma.sync.aligned.m16n8k16.row.col.f32.bf16.bf16.f32 "
        "{%0,%1,%2,%3}, {%4,%5,%6,%7}, {%8,%9}, {%0,%1,%2,%3};"
        : "+f"(d[0]), "+f"(d[1]), "+f"(d[2]), "+f"(d[3])
        : "r"(a[0]), "r"(a[1]), "r"(a[2]), "r"(a[3]), "r"(b0), "r"(b1));
}

// smem tile: 128 rows x 32 k, padded row stride 40 bf16 (80 B -> conflict-free
// ldmatrix phases: 8 rows * 20 banks mod 32 all distinct)
#define TPAD 40

__device__ __forceinline__ void stage8_cvt(const float* __restrict__ p,
                                           __nv_bfloat16* __restrict__ hi,
                                           __nv_bfloat16* __restrict__ lo,
                                           int idx) {
    float4 u = *(const float4*)p;
    float4 v = *(const float4*)(p + 4);
    float xs[8] = {u.x, u.y, u.z, u.w, v.x, v.y, v.z, v.w};
    uint32_t hw[4], lw[4];
#pragma unroll
    for (int q = 0; q < 4; q++) {
        __nv_bfloat16 h0 = __float2bfloat16_rn(xs[2*q]);
        __nv_bfloat16 h1 = __float2bfloat16_rn(xs[2*q+1]);
        hw[q] = (uint32_t)__bfloat16_as_ushort(h0) | ((uint32_t)__bfloat16_as_ushort(h1) << 16);
        __nv_bfloat16 l0 = __float2bfloat16_rn(xs[2*q]   - __bfloat162float(h0));
        __nv_bfloat16 l1 = __float2bfloat16_rn(xs[2*q+1] - __bfloat162float(h1));
        lw[q] = (uint32_t)__bfloat16_as_ushort(l0) | ((uint32_t)__bfloat16_as_ushort(l1) << 16);
    }
    *(uint4*)(hi + idx) = make_uint4(hw[0], hw[1], hw[2], hw[3]);
    *(uint4*)(lo + idx) = make_uint4(lw[0], lw[1], lw[2], lw[3]);
}

// Core: C[128,128] (this block) = A[128,K] @ B[128,K]^T, bf16x3 compensated.
// acc[mi][nj][r]: warp (wid/4)*64 + mi*16 rows, (wid%4)*32 + nj*8 cols.
template<int KCH>   // number of 32-wide K chunks
__device__ __forceinline__ void gemm_core(const float* __restrict__ Asrc, int astr,
                                          const float* __restrict__ Bsrc, int bstr,
                                          float acc[4][4][4],
                                          __nv_bfloat16* sAhi, __nv_bfloat16* sAlo,
                                          __nv_bfloat16* sBhi, __nv_bfloat16* sBlo)
{
    const int tid = threadIdx.x;
    const int wid = tid >> 5, lane = tid & 31;
    const int wm = (wid >> 2) * 64;
    const int wn = (wid & 3) * 32;
    const int arow = wm + (lane & 15);
    const int akc  = (lane >> 4) * 8;
    const int brow = wn + (lane >> 4) * 8 + (lane & 7);
    const int bkc  = ((lane >> 3) & 1) * 8;

    for (int ch = 0; ch < KCH; ch++) {
        const int k0 = ch * 32;
#pragma unroll
        for (int i = 0; i < 2; i++) {
            int g = tid + i * 256;            // 512 octet slots
            int row = g >> 2, oct = g & 3;
            stage8_cvt(Asrc + (size_t)row * astr + k0 + oct * 8, sAhi, sAlo, row * TPAD + oct * 8);
        }
#pragma unroll
        for (int i = 0; i < 2; i++) {
            int g = tid + i * 256;
            int row = g >> 2, oct = g & 3;
            stage8_cvt(Bsrc + (size_t)row * bstr + k0 + oct * 8, sBhi, sBlo, row * TPAD + oct * 8);
        }
        __syncthreads();

#pragma unroll
        for (int ks = 0; ks < 2; ks++) {
            const int kc = ks * 16;
            uint32_t ahi[4][4], alo[4][4];
#pragma unroll
            for (int mi = 0; mi < 4; mi++) {
                const int off = (arow + mi * 16) * TPAD + kc + akc;
                ldmx4(ahi[mi], sAhi + off);
                ldmx4(alo[mi], sAlo + off);
            }
            uint32_t bhi[2][4], blo[2][4];
#pragma unroll
            for (int np = 0; np < 2; np++) {
                const int off = (brow + np * 16) * TPAD + kc + bkc;
                ldmx4(bhi[np], sBhi + off);
                ldmx4(blo[np], sBlo + off);
            }
#pragma unroll
            for (int mi = 0; mi < 4; mi++)
#pragma unroll
                for (int nj = 0; nj < 4; nj++) {
                    const int np = nj >> 1, o = (nj & 1) * 2;
                    mma16816(acc[mi][nj], ahi[mi], bhi[np][o], bhi[np][o+1]);
                    mma16816(acc[mi][nj], ahi[mi], blo[np][o], blo[np][o+1]);
                    mma16816(acc[mi][nj], alo[mi], bhi[np][o], bhi[np][o+1]);
                }
        }
        __syncthreads();
    }
}

// ============================================================================
// Kernel 1 (mma): qkva[row, n] = X[row,:] . Wcat[n,:]
// ============================================================================
__global__ void __launch_bounds__(256) k_proj_mma(const float* __restrict__ X,
                                                  const float* __restrict__ Wq,
                                                  const float* __restrict__ Wk,
                                                  const float* __restrict__ Wv,
                                                  const float* __restrict__ Wa)
{
    __shared__ __nv_bfloat16 sAhi[128 * TPAD], sAlo[128 * TPAD];
    __shared__ __nv_bfloat16 sBhi[128 * TPAD], sBlo[128 * TPAD];

    const int bn = blockIdx.x;            // 0..7
    const int bm = blockIdx.y;            // 0..127
    const int which = bn >> 1;
    const float* W = (which == 0) ? Wq : (which == 1) ? Wk : (which == 2) ? Wv : Wa;
    const float* Bsrc = W + (size_t)(bn & 1) * 128 * DLEN;
    const float* Asrc = X + (size_t)bm * 128 * DLEN;

    float acc[4][4][4] = {};
    gemm_core<16>(Asrc, DLEN, Bsrc, DLEN, acc, sAhi, sAlo, sBhi, sBlo);

    const int tid = threadIdx.x;
    const int wid = tid >> 5, lane = tid & 31;
    const int r0 = bm * 128 + (wid >> 2) * 64 + (lane >> 2);
    const int c0 = bn * 128 + (wid & 3) * 32 + (lane & 3) * 2;
#pragma unroll
    for (int mi = 0; mi < 4; mi++)
#pragma unroll
        for (int nj = 0; nj < 4; nj++) {
            int r = r0 + mi * 16, c = c0 + nj * 8;
            *(float2*)&g_qkva[(size_t)r * NPROJ + c]       = make_float2(acc[mi][nj][0], acc[mi][nj][1]);
            *(float2*)&g_qkva[(size_t)(r + 8) * NPROJ + c] = make_float2(acc[mi][nj][2], acc[mi][nj][3]);
        }
}

// ============================================================================
// Kernel 2: per-row scale = exp(0.5*||q||^2) / sqrt(M),  for Q and K halves.
// ============================================================================
__global__ void k_rowscale()
{
    int warp = (blockIdx.x * blockDim.x + threadIdx.x) >> 5;
    int lane = threadIdx.x & 31;
    int isK = blockIdx.y;
    if (warp >= BL) return;
    const float* row = g_qkva + (size_t)warp * NPROJ + (isK ? DM : 0);
    float s = 0.f;
#pragma unroll
    for (int i = lane; i < DM; i += 32) { float v = row[i]; s = fmaf(v, v, s); }
#pragma unroll
    for (int o = 16; o; o >>= 1) s += __shfl_xor_sync(0xFFFFFFFFu, s, o);
    if (lane == 0) {
        float sc = expf(0.5f * s) * 0.0625f;   // 1/sqrt(256) = 1/16
        (isK ? g_scale_k : g_scale_q)[warp] = sc;
    }
}

// ============================================================================
// Kernel 3 (mma): phi.  proj = (Q or K)[128,256] @ rf[128-tile,256]^T,
// epilogue sincos * rowscale -> qp/kp.
// ============================================================================
__global__ void __launch_bounds__(256) k_phi_mma(const float* __restrict__ rf)
{
    __shared__ __nv_bfloat16 sAhi[128 * TPAD], sAlo[128 * TPAD];
    __shared__ __nv_bfloat16 sBhi[128 * TPAD], sBlo[128 * TPAD];

    const int bn = blockIdx.x;            // 0..1
    const int bm = blockIdx.y;            // 0..127
    const int isK = blockIdx.z;
    const float* Asrc = g_qkva + (size_t)bm * 128 * NPROJ + (isK ? DM : 0);
    const float* Bsrc = rf + (size_t)bn * 128 * MRF;

    float acc[4][4][4] = {};
    gemm_core<8>(Asrc, NPROJ, Bsrc, MRF, acc, sAhi, sAlo, sBhi, sBlo);

    float* OUT = isK ? g_kp : g_qp;
    const float* SC = isK ? g_scale_k : g_scale_q;

    const int tid = threadIdx.x;
    const int wid = tid >> 5, lane = tid & 31;
    const int r0 = bm * 128 + (wid >> 2) * 64 + (lane >> 2);
    const int c0 = bn * 128 + (wid & 3) * 32 + (lane & 3) * 2;
#pragma unroll
    for (int mi = 0; mi < 4; mi++) {
        int r  = r0 + mi * 16;
        float sa = SC[r], sb = SC[r + 8];
        float* rowa = OUT + (size_t)r * TWOM;
        float* rowb = OUT + (size_t)(r + 8) * TWOM;
#pragma unroll
        for (int nj = 0; nj < 4; nj++) {
            int c = c0 + nj * 8;
            float s0, cz0, s1, cz1, s2, cz2, s3, cz3;
            sincosf(TWO_PI * acc[mi][nj][0], &s0, &cz0);
            sincosf(TWO_PI * acc[mi][nj][1], &s1, &cz1);
            sincosf(TWO_PI * acc[mi][nj][2], &s2, &cz2);
            sincosf(TWO_PI * acc[mi][nj][3], &s3, &cz3);
            *(float2*)&rowa[c]      = make_float2(s0 * sa,  s1 * sa);
            *(float2*)&rowa[c + DM] = make_float2(cz0 * sa, cz1 * sa);
            *(float2*)&rowb[c]      = make_float2(s2 * sb,  s3 * sb);
            *(float2*)&rowb[c + DM] = make_float2(cz2 * sb, cz3 * sb);
        }
    }
}

// ============================================================================
// Kernel 4: ksum[b, m] = sum_l kp[b, l, m].
// ============================================================================
__global__ void k_ksum()
{
    const int b = blockIdx.y;
    const int mi = threadIdx.x & 63;
    const int m = blockIdx.x * 64 + mi;
    const int lg = threadIdx.x >> 6;
    const float* base = g_kp + ((size_t)b * LSEQ + lg) * TWOM + m;
    float s = 0.f;
    for (int l = 0; l < LSEQ; l += 4) s += base[(size_t)l * TWOM];
    __shared__ float red[4][64];
    red[lg][mi] = s;
    __syncthreads();
    if (lg == 0)
        g_ksum[b * TWOM + m] = red[0][mi] + red[1][mi] + red[2][mi] + red[3][mi];
}

// ============================================================================
// Kernel 5: kv[b, m, d] = sum_l kp[b,l,m] * v[b,l,d]   (TN, contraction = l)
// ============================================================================
__global__ void __launch_bounds__(256) k_kv()
{
    const int d0 = blockIdx.x * 64;
    const int m0 = blockIdx.y * 64;
    const int b  = blockIdx.z;

    const float* Kbase = g_kp + (size_t)b * LSEQ * TWOM;        // [l, 512]
    const float* Vbase = g_qkva + (size_t)b * LSEQ * NPROJ + 2 * DM;  // V cols

    __shared__ float As[16][68];
    __shared__ float Bs[16][68];

    const int tid = threadIdx.x;
    const int tx = tid & 15, ty = tid >> 4;
    const int lt  = tid >> 4;          // 0..15 load row
    const int mi4 = (tid & 15) * 4;    // 0..60 load col

    float acc[4][4] = {};

    for (int l0 = 0; l0 < LSEQ; l0 += 16) {
        {
            float4 t = *(const float4*)(Kbase + (size_t)(l0 + lt) * TWOM + m0 + mi4);
            As[lt][mi4] = t.x; As[lt][mi4+1] = t.y; As[lt][mi4+2] = t.z; As[lt][mi4+3] = t.w;
            float4 u = *(const float4*)(Vbase + (size_t)(l0 + lt) * NPROJ + d0 + mi4);
            Bs[lt][mi4] = u.x; Bs[lt][mi4+1] = u.y; Bs[lt][mi4+2] = u.z; Bs[lt][mi4+3] = u.w;
        }
        __syncthreads();
#pragma unroll
        for (int k = 0; k < 16; k++) {
            float a[4], bb[4];
#pragma unroll
            for (int i = 0; i < 4; i++) a[i] = As[k][ty * 4 + i];
#pragma unroll
            for (int j = 0; j < 4; j++) bb[j] = Bs[k][tx * 4 + j];
#pragma unroll
            for (int i = 0; i < 4; i++)
#pragma unroll
                for (int j = 0; j < 4; j++)
                    acc[i][j] = fmaf(a[i], bb[j], acc[i][j]);
        }
        __syncthreads();
    }

#pragma unroll
    for (int i = 0; i < 4; i++) {
        float* p = g_kv + ((size_t)b * TWOM + m0 + ty * 4 + i) * DM + d0 + tx * 4;
        *(float4*)p = make_float4(acc[i][0], acc[i][1], acc[i][2], acc[i][3]);
    }
}

// ============================================================================
// Kernel 6: denom[row] = sum_m qp[row,m] * ksum[b,m].
// ============================================================================
__global__ void k_denom()
{
    int warp = (blockIdx.x * blockDim.x + threadIdx.x) >> 5;
    int lane = threadIdx.x & 31;
    if (warp >= BL) return;
    const float* q  = g_qp  + (size_t)warp * TWOM;
    const float* ks = g_ksum + (size_t)(warp >> 11) * TWOM;
    float s = 0.f;
#pragma unroll
    for (int i = lane; i < TWOM; i += 32) s = fmaf(q[i], ks[i], s);
#pragma unroll
    for (int o = 16; o; o >>= 1) s += __shfl_xor_sync(0xFFFFFFFFu, s, o);
    if (lane == 0) g_denom[warp] = s;
}

// ============================================================================
// Kernel 7: num[b,l,d] = sum_m qp[b,l,m] * kv[b,m,d]  (NN), fused epilogue:
//   out = num/denom + addproj + b_add   -> g_out
// ============================================================================
__global__ void __launch_bounds__(256) k_num(const float* __restrict__ b_add)
{
    const int bn = blockIdx.x;            // 0..1 d tile
    const int bm = blockIdx.y;            // 0..15 l tile
    const int b  = blockIdx.z;

    const float* Abase = g_qp + ((size_t)(b * LSEQ + bm * 128)) * TWOM;  // [l,512]
    const float* Bbase = g_kv + (size_t)b * TWOM * DM + bn * 128;        // [m,256]

    __shared__ float As[16][132];
    __shared__ float Bs[16][132];

    const int tid = threadIdx.x;
    const int tx = tid & 15, ty = tid >> 4;

    float acc[8][8] = {};

    for (int k0 = 0; k0 < TWOM; k0 += 16) {
#pragma unroll
        for (int i = 0; i < 2; i++) {
            int v = tid + i * 256;
            int row = v >> 2, kq = v & 3;       // A: transpose load
            float4 t = *(const float4*)(Abase + (size_t)row * TWOM + k0 + kq * 4);
            As[kq*4+0][row] = t.x; As[kq*4+1][row] = t.y;
            As[kq*4+2][row] = t.z; As[kq*4+3][row] = t.w;
        }
#pragma unroll
        for (int i = 0; i < 2; i++) {
            int v = tid + i * 256;
            int kt = v >> 5, d4 = (v & 31) * 4;  // B: direct load
            float4 t = *(const float4*)(Bbase + (size_t)(k0 + kt) * DM + d4);
            Bs[kt][d4] = t.x; Bs[kt][d4+1] = t.y; Bs[kt][d4+2] = t.z; Bs[kt][d4+3] = t.w;
        }
        __syncthreads();
#pragma unroll
        for (int k = 0; k < 16; k++) {
            float a[8], bb[8];
#pragma unroll
            for (int i = 0; i < 8; i++) a[i] = As[k][ty * 8 + i];
#pragma unroll
            for (int j = 0; j < 8; j++) bb[j] = Bs[k][tx * 8 + j];
#pragma unroll
            for (int i = 0; i < 8; i++)
#pragma unroll
                for (int j = 0; j < 8; j++)
                    acc[i][j] = fmaf(a[i], bb[j], acc[i][j]);
        }
        __syncthreads();
    }

    const int dbase = bn * 128 + tx * 8;
#pragma unroll
    for (int i = 0; i < 8; i++) {
        int r = b * LSEQ + bm * 128 + ty * 8 + i;     // global row
        float den = g_denom[r];
        const float* addp = g_qkva + (size_t)r * NPROJ + 3 * DM + dbase;
        float* orow = g_out + (size_t)r * DM + dbase;
#pragma unroll
        for (int j = 0; j < 8; j++) {
            orow[j] = acc[i][j] / den + addp[j] + b_add[dbase + j];
        }
    }
}

// ============================================================================
// Kernel 8a: init d_out with b_final.
// ============================================================================
__global__ void k_init_out(float* __restrict__ out, const float* __restrict__ bf)
{
    int i = threadIdx.x;                 // 512 threads
    out[i] = bf[i & 63];
}

// ============================================================================
// Kernel 8b: result[b,c] += sum_f out[b,f] * Wf[c,f]   (split-K, atomics)
// ============================================================================
__global__ void __launch_bounds__(256) k_final(const float* __restrict__ Wf,
                                               float* __restrict__ out)
{
    __shared__ float Ws[64][130];
    __shared__ float Os[8][132];

    const int tid = threadIdx.x;
    const int c  = tid & 63;
    const int bb = tid >> 6;             // 0..3
    float acc0 = 0.f, acc1 = 0.f;
    const int f0 = blockIdx.x * 1024;

    for (int t = 0; t < 1024; t += 128) {
        const int fbase = f0 + t;
#pragma unroll
        for (int i = 0; i < 8; i++) {    // Ws: 2048 float4 / 256 thr
            int v = tid + i * 256;
            int cc = v >> 5, f4 = (v & 31) * 4;
            float4 w = *(const float4*)(Wf + (size_t)cc * FTOT + fbase + f4);
            Ws[cc][f4] = w.x; Ws[cc][f4+1] = w.y; Ws[cc][f4+2] = w.z; Ws[cc][f4+3] = w.w;
        }
        {                                // Os: 256 float4 / 256 thr
            int v = tid;
            int bo = v >> 5, f4 = (v & 31) * 4;
            float4 o = *(const float4*)(g_out + (size_t)bo * FTOT + fbase + f4);
            Os[bo][f4] = o.x; Os[bo][f4+1] = o.y; Os[bo][f4+2] = o.z; Os[bo][f4+3] = o.w;
        }
        __syncthreads();
#pragma unroll 8
        for (int fi = 0; fi < 128; fi++) {
            float w = Ws[c][fi];
            acc0 = fmaf(Os[bb][fi],     w, acc0);
            acc1 = fmaf(Os[bb + 4][fi], w, acc1);
        }
        __syncthreads();
    }
    atomicAdd(&out[bb * NCLASS + c],       acc0);
    atomicAdd(&out[(bb + 4) * NCLASS + c], acc1);
}

// ============================================================================
extern "C" void kernel_launch(void* const* d_in, const int* in_sizes, int n_in,
                              void* d_out, int out_size)
{
    const float* X  = (const float*)d_in[0];
    // d_in[1..6]: unused scalars
    const float* Wq = (const float*)d_in[7];
    const float* Wk = (const float*)d_in[8];
    const float* Wv = (const float*)d_in[9];
    const float* Wa = (const float*)d_in[10];
    const float* bA = (const float*)d_in[11];
    const float* Wf = (const float*)d_in[12];
    const float* bF = (const float*)d_in[13];
    const float* rf = (const float*)d_in[14];
    float* out = (float*)d_out;

    k_proj_mma<<<dim3(8, 128),    256>>>(X, Wq, Wk, Wv, Wa);
    k_rowscale<<<dim3(2048, 2),   256>>>();
    k_phi_mma <<<dim3(2, 128, 2), 256>>>(rf);
    k_ksum    <<<dim3(8, 8),      256>>>();
    k_kv      <<<dim3(4, 8, 8),   256>>>();
    k_denom   <<<2048,            256>>>();
    k_num     <<<dim3(2, 16, 8),  256>>>(bA);
    k_init_out<<<1, 512>>>(out, bF);
    k_final   <<<512, 256>>>(Wf, out);
}

// round 6
// speedup vs baseline: 1.4621x; 1.1216x over previous
#include <cuda_runtime.h>
#include <cuda_bf16.h>
#include <math.h>
#include <cstdint>

// Problem constants
#define NB     8
#define LSEQ   2048
#define BL     16384          // NB*LSEQ
#define DLEN   512
#define DM     256
#define NPROJ  1024           // Q|K|V|Add concatenated
#define MRF    256
#define TWOM   512
#define NCLASS 64
#define FTOT   (LSEQ*DM)      // 524288 flattened features per batch

#define TWO_PI 6.28318530717958647692f

// ---------------- device scratch (allocation-free rule: static globals) ----
__device__ float g_qkva[BL * NPROJ];      // 64 MB : [row, 1024] = Q|K|V|Add
__device__ float g_scale_q[BL];
__device__ float g_scale_k[BL];
__device__ float g_qp[BL * TWOM];         // 32 MB
__device__ float g_kp[BL * TWOM];         // 32 MB
__device__ float g_ksum[NB * TWOM];
__device__ float g_kv[NB * TWOM * DM];    // 4 MB
__device__ float g_out[BL * DM];          // 16 MB (== [b, FTOT] flat)

// ============================================================================
// mma.sync helpers (baseline PTX — valid at compute_100, no 'a' features)
// ============================================================================
__device__ __forceinline__ uint32_t smem_u32(const void* p) {
    uint32_t a;
    asm("{ .reg .u64 t; cvta.to.shared.u64 t, %1; cvt.u32.u64 %0, t; }" : "=r"(a) : "l"(p));
    return a;
}

__device__ __forceinline__ void ldmx4(uint32_t r[4], const void* p) {
    uint32_t a = smem_u32(p);
    asm volatile("ldmatrix.sync.aligned.m8n8.x4.shared.b16 {%0,%1,%2,%3}, [%4];"
                 : "=r"(r[0]), "=r"(r[1]), "=r"(r[2]), "=r"(r[3]) : "r"(a));
}
__device__ __forceinline__ void ldmx4t(uint32_t r[4], const void* p) {
    uint32_t a = smem_u32(p);
    asm volatile("ldmatrix.sync.aligned.m8n8.x4.trans.shared.b16 {%0,%1,%2,%3}, [%4];"
                 : "=r"(r[0]), "=r"(r[1]), "=r"(r[2]), "=r"(r[3]) : "r"(a));
}

__device__ __forceinline__ void mma16816(float d[4], const uint32_t a[4],
                                         uint32_t b0, uint32_t b1) {
    asm volatile(
        "mma.sync.aligned.m16n8k16.row.col.f32.bf16.bf16.f32 "
        "{%0,%1,%2,%3}, {%4,%5,%6,%7}, {%8,%9}, {%0,%1,%2,%3};"
        : "+f"(d[0]), "+f"(d[1]), "+f"(d[2]), "+f"(d[3])
        : "r"(a[0]), "r"(a[1]), "r"(a[2]), "r"(a[3]), "r"(b0), "r"(b1));
}

// padded smem row strides (bf16 units) chosen so 8 consecutive rows hit
// distinct bank groups for (trans-)ldmatrix phases.
#define TPAD 40    // [row][32 k]  tiles (stride 40 -> step 20 banks)
#define KTP  136   // [32 k][128 c] tiles (stride 136 -> step 4 banks)
#define KTPB 72    // [32 k][64 c]  tiles (stride 72  -> step 4 banks)

__device__ __forceinline__ void cvt8(const float xs[8], uint32_t hw[4], uint32_t lw[4]) {
#pragma unroll
    for (int q = 0; q < 4; q++) {
        __nv_bfloat16 h0 = __float2bfloat16_rn(xs[2*q]);
        __nv_bfloat16 h1 = __float2bfloat16_rn(xs[2*q+1]);
        hw[q] = (uint32_t)__bfloat16_as_ushort(h0) | ((uint32_t)__bfloat16_as_ushort(h1) << 16);
        __nv_bfloat16 l0 = __float2bfloat16_rn(xs[2*q]   - __bfloat162float(h0));
        __nv_bfloat16 l1 = __float2bfloat16_rn(xs[2*q+1] - __bfloat162float(h1));
        lw[q] = (uint32_t)__bfloat16_as_ushort(l0) | ((uint32_t)__bfloat16_as_ushort(l1) << 16);
    }
}

__device__ __forceinline__ void stage8_cvt(const float* __restrict__ p,
                                           __nv_bfloat16* __restrict__ hi,
                                           __nv_bfloat16* __restrict__ lo,
                                           int idx) {
    float4 u = *(const float4*)p;
    float4 v = *(const float4*)(p + 4);
    float xs[8] = {u.x, u.y, u.z, u.w, v.x, v.y, v.z, v.w};
    uint32_t hw[4], lw[4];
    cvt8(xs, hw, lw);
    *(uint4*)(hi + idx) = make_uint4(hw[0], hw[1], hw[2], hw[3]);
    *(uint4*)(lo + idx) = make_uint4(lw[0], lw[1], lw[2], lw[3]);
}

// Core: C[128,128] (this block) = A[128,K] @ B[128,K]^T, bf16x3 compensated.
template<int KCH>   // number of 32-wide K chunks
__device__ __forceinline__ void gemm_core(const float* __restrict__ Asrc, int astr,
                                          const float* __restrict__ Bsrc, int bstr,
                                          float acc[4][4][4],
                                          __nv_bfloat16* sAhi, __nv_bfloat16* sAlo,
                                          __nv_bfloat16* sBhi, __nv_bfloat16* sBlo)
{
    const int tid = threadIdx.x;
    const int wid = tid >> 5, lane = tid & 31;
    const int wm = (wid >> 2) * 64;
    const int wn = (wid & 3) * 32;
    const int arow = wm + (lane & 15);
    const int akc  = (lane >> 4) * 8;
    const int brow = wn + (lane >> 4) * 8 + (lane & 7);
    const int bkc  = ((lane >> 3) & 1) * 8;

    for (int ch = 0; ch < KCH; ch++) {
        const int k0 = ch * 32;
#pragma unroll
        for (int i = 0; i < 2; i++) {
            int g = tid + i * 256;            // 512 octet slots
            int row = g >> 2, oct = g & 3;
            stage8_cvt(Asrc + (size_t)row * astr + k0 + oct * 8, sAhi, sAlo, row * TPAD + oct * 8);
        }
#pragma unroll
        for (int i = 0; i < 2; i++) {
            int g = tid + i * 256;
            int row = g >> 2, oct = g & 3;
            stage8_cvt(Bsrc + (size_t)row * bstr + k0 + oct * 8, sBhi, sBlo, row * TPAD + oct * 8);
        }
        __syncthreads();

#pragma unroll
        for (int ks = 0; ks < 2; ks++) {
            const int kc = ks * 16;
            uint32_t ahi[4][4], alo[4][4];
#pragma unroll
            for (int mi = 0; mi < 4; mi++) {
                const int off = (arow + mi * 16) * TPAD + kc + akc;
                ldmx4(ahi[mi], sAhi + off);
                ldmx4(alo[mi], sAlo + off);
            }
            uint32_t bhi[2][4], blo[2][4];
#pragma unroll
            for (int np = 0; np < 2; np++) {
                const int off = (brow + np * 16) * TPAD + kc + bkc;
                ldmx4(bhi[np], sBhi + off);
                ldmx4(blo[np], sBlo + off);
            }
#pragma unroll
            for (int mi = 0; mi < 4; mi++)
#pragma unroll
                for (int nj = 0; nj < 4; nj++) {
                    const int np = nj >> 1, o = (nj & 1) * 2;
                    mma16816(acc[mi][nj], ahi[mi], bhi[np][o], bhi[np][o+1]);
                    mma16816(acc[mi][nj], ahi[mi], blo[np][o], blo[np][o+1]);
                    mma16816(acc[mi][nj], alo[mi], bhi[np][o], bhi[np][o+1]);
                }
        }
        __syncthreads();
    }
}

// ============================================================================
// Kernel 1 (mma): qkva[row, n] = X[row,:] . Wcat[n,:]
// ============================================================================
__global__ void __launch_bounds__(256) k_proj_mma(const float* __restrict__ X,
                                                  const float* __restrict__ Wq,
                                                  const float* __restrict__ Wk,
                                                  const float* __restrict__ Wv,
                                                  const float* __restrict__ Wa)
{
    __shared__ __nv_bfloat16 sAhi[128 * TPAD], sAlo[128 * TPAD];
    __shared__ __nv_bfloat16 sBhi[128 * TPAD], sBlo[128 * TPAD];

    const int bn = blockIdx.x;            // 0..7
    const int bm = blockIdx.y;            // 0..127
    const int which = bn >> 1;
    const float* W = (which == 0) ? Wq : (which == 1) ? Wk : (which == 2) ? Wv : Wa;
    const float* Bsrc = W + (size_t)(bn & 1) * 128 * DLEN;
    const float* Asrc = X + (size_t)bm * 128 * DLEN;

    float acc[4][4][4] = {};
    gemm_core<16>(Asrc, DLEN, Bsrc, DLEN, acc, sAhi, sAlo, sBhi, sBlo);

    const int tid = threadIdx.x;
    const int wid = tid >> 5, lane = tid & 31;
    const int r0 = bm * 128 + (wid >> 2) * 64 + (lane >> 2);
    const int c0 = bn * 128 + (wid & 3) * 32 + (lane & 3) * 2;
#pragma unroll
    for (int mi = 0; mi < 4; mi++)
#pragma unroll
        for (int nj = 0; nj < 4; nj++) {
            int r = r0 + mi * 16, c = c0 + nj * 8;
            *(float2*)&g_qkva[(size_t)r * NPROJ + c]       = make_float2(acc[mi][nj][0], acc[mi][nj][1]);
            *(float2*)&g_qkva[(size_t)(r + 8) * NPROJ + c] = make_float2(acc[mi][nj][2], acc[mi][nj][3]);
        }
}

// ============================================================================
// Kernel 2: per-row scale = exp(0.5*||q||^2) / sqrt(M),  for Q and K halves.
// ============================================================================
__global__ void k_rowscale()
{
    int warp = (blockIdx.x * blockDim.x + threadIdx.x) >> 5;
    int lane = threadIdx.x & 31;
    int isK = blockIdx.y;
    if (warp >= BL) return;
    const float* row = g_qkva + (size_t)warp * NPROJ + (isK ? DM : 0);
    float s = 0.f;
#pragma unroll
    for (int i = lane; i < DM; i += 32) { float v = row[i]; s = fmaf(v, v, s); }
#pragma unroll
    for (int o = 16; o; o >>= 1) s += __shfl_xor_sync(0xFFFFFFFFu, s, o);
    if (lane == 0) {
        float sc = expf(0.5f * s) * 0.0625f;   // 1/sqrt(256) = 1/16
        (isK ? g_scale_k : g_scale_q)[warp] = sc;
    }
}

// ============================================================================
// Kernel 3 (mma): phi.  proj = (Q or K)[128,256] @ rf[128-tile,256]^T,
// epilogue sincos * rowscale -> qp/kp.
// ============================================================================
__global__ void __launch_bounds__(256) k_phi_mma(const float* __restrict__ rf)
{
    __shared__ __nv_bfloat16 sAhi[128 * TPAD], sAlo[128 * TPAD];
    __shared__ __nv_bfloat16 sBhi[128 * TPAD], sBlo[128 * TPAD];

    const int bn = blockIdx.x;            // 0..1
    const int bm = blockIdx.y;            // 0..127
    const int isK = blockIdx.z;
    const float* Asrc = g_qkva + (size_t)bm * 128 * NPROJ + (isK ? DM : 0);
    const float* Bsrc = rf + (size_t)bn * 128 * MRF;

    float acc[4][4][4] = {};
    gemm_core<8>(Asrc, NPROJ, Bsrc, MRF, acc, sAhi, sAlo, sBhi, sBlo);

    float* OUT = isK ? g_kp : g_qp;
    const float* SC = isK ? g_scale_k : g_scale_q;

    const int tid = threadIdx.x;
    const int wid = tid >> 5, lane = tid & 31;
    const int r0 = bm * 128 + (wid >> 2) * 64 + (lane >> 2);
    const int c0 = bn * 128 + (wid & 3) * 32 + (lane & 3) * 2;
#pragma unroll
    for (int mi = 0; mi < 4; mi++) {
        int r  = r0 + mi * 16;
        float sa = SC[r], sb = SC[r + 8];
        float* rowa = OUT + (size_t)r * TWOM;
        float* rowb = OUT + (size_t)(r + 8) * TWOM;
#pragma unroll
        for (int nj = 0; nj < 4; nj++) {
            int c = c0 + nj * 8;
            float s0, cz0, s1, cz1, s2, cz2, s3, cz3;
            sincosf(TWO_PI * acc[mi][nj][0], &s0, &cz0);
            sincosf(TWO_PI * acc[mi][nj][1], &s1, &cz1);
            sincosf(TWO_PI * acc[mi][nj][2], &s2, &cz2);
            sincosf(TWO_PI * acc[mi][nj][3], &s3, &cz3);
            *(float2*)&rowa[c]      = make_float2(s0 * sa,  s1 * sa);
            *(float2*)&rowa[c + DM] = make_float2(cz0 * sa, cz1 * sa);
            *(float2*)&rowb[c]      = make_float2(s2 * sb,  s3 * sb);
            *(float2*)&rowb[c + DM] = make_float2(cz2 * sb, cz3 * sb);
        }
    }
}

// ============================================================================
// Kernel 4 (mma): kv[b, m, d] = sum_l kp[b,l,m] * v[b,l,d]  (both via trans)
// Block tile: 128 m x 64 d, K = L in 32-chunks. Fused: ksum (d-tile 0).
// ============================================================================
__global__ void __launch_bounds__(256) k_kv_mma()
{
    __shared__ __nv_bfloat16 sAhi[32 * KTP],  sAlo[32 * KTP];    // kp chunk [l][m]
    __shared__ __nv_bfloat16 sBhi[32 * KTPB], sBlo[32 * KTPB];   // v  chunk [l][d]
    __shared__ float red[16][128];

    const int d0 = blockIdx.x * 64;       // 0..3
    const int m0 = blockIdx.y * 128;      // 0..3
    const int b  = blockIdx.z;
    const float* kpb = g_kp   + (size_t)b * LSEQ * TWOM  + m0;
    const float* vb  = g_qkva + (size_t)b * LSEQ * NPROJ + 2 * DM + d0;

    const int tid = threadIdx.x, wid = tid >> 5, lane = tid & 31;
    const int g8 = lane >> 3, r8 = lane & 7;
    const int wm = (wid >> 2) * 64, wn = (wid & 3) * 16;

    float acc[4][2][4] = {};
    float ksp[8] = {};

    const int arow0 = tid >> 4, acol8 = (tid & 15) * 8;   // A staging slots
    const int brow0 = tid >> 3, bcol8 = (tid & 7) * 8;    // B staging slot

    for (int ch = 0; ch < LSEQ / 32; ch++) {
        const int l0 = ch * 32;
#pragma unroll
        for (int i = 0; i < 2; i++) {
            int row = arow0 + i * 16;
            const float* p = kpb + (size_t)(l0 + row) * TWOM + acol8;
            float4 u = *(const float4*)p, v4 = *(const float4*)(p + 4);
            float xs[8] = {u.x, u.y, u.z, u.w, v4.x, v4.y, v4.z, v4.w};
            uint32_t hw[4], lw[4];
            cvt8(xs, hw, lw);
#pragma unroll
            for (int q = 0; q < 8; q++) ksp[q] += xs[q];
            *(uint4*)(sAhi + row * KTP + acol8) = make_uint4(hw[0], hw[1], hw[2], hw[3]);
            *(uint4*)(sAlo + row * KTP + acol8) = make_uint4(lw[0], lw[1], lw[2], lw[3]);
        }
        stage8_cvt(vb + (size_t)(l0 + brow0) * NPROJ + bcol8, sBhi, sBlo, brow0 * KTPB + bcol8);
        __syncthreads();

#pragma unroll
        for (int ks = 0; ks < 2; ks++) {
            const int kc = ks * 16;
            uint32_t ahi[4][4], alo[4][4];
#pragma unroll
            for (int mi = 0; mi < 4; mi++) {
                // A = kp^T via trans: mats {(m0-7,k0-7),(m8-15,k0-7),(m0-7,k8-15),(m8-15,k8-15)}
                const int off = (kc + r8 + (g8 >> 1) * 8) * KTP + wm + mi * 16 + (g8 & 1) * 8;
                ldmx4t(ahi[mi], sAhi + off);
                ldmx4t(alo[mi], sAlo + off);
            }
            uint32_t bhi[4], blo[4];
            {
                // B = v^T via trans: mats {(n0-7,k0-7),(n0-7,k8-15),(n8-15,k0-7),(n8-15,k8-15)}
                const int off = (kc + r8 + (g8 & 1) * 8) * KTPB + wn + (g8 >> 1) * 8;
                ldmx4t(bhi, sBhi + off);
                ldmx4t(blo, sBlo + off);
            }
#pragma unroll
            for (int mi = 0; mi < 4; mi++)
#pragma unroll
                for (int nj = 0; nj < 2; nj++) {
                    const int o = nj * 2;
                    mma16816(acc[mi][nj], ahi[mi], bhi[o], bhi[o+1]);
                    mma16816(acc[mi][nj], ahi[mi], blo[o], blo[o+1]);
                    mma16816(acc[mi][nj], alo[mi], bhi[o], bhi[o+1]);
                }
        }
        __syncthreads();
    }

    const int rr0 = m0 + wm + (lane >> 2);
    const int cc0 = d0 + wn + (lane & 3) * 2;
#pragma unroll
    for (int mi = 0; mi < 4; mi++)
#pragma unroll
        for (int nj = 0; nj < 2; nj++) {
            int r = rr0 + mi * 16, c = cc0 + nj * 8;
            *(float2*)&g_kv[((size_t)b * TWOM + r) * DM + c]     = make_float2(acc[mi][nj][0], acc[mi][nj][1]);
            *(float2*)&g_kv[((size_t)b * TWOM + r + 8) * DM + c] = make_float2(acc[mi][nj][2], acc[mi][nj][3]);
        }

    if (blockIdx.x == 0) {   // fused ksum for this m-tile
#pragma unroll
        for (int q = 0; q < 8; q++) red[arow0][acol8 + q] = ksp[q];
        __syncthreads();
        if (tid < 128) {
            float s = 0.f;
#pragma unroll
            for (int j = 0; j < 16; j++) s += red[j][tid];
            g_ksum[b * TWOM + m0 + tid] = s;
        }
    }
}

// ============================================================================
// Kernel 5 (mma): num[b,l,d] = sum_m qp[b,l,m] * kv[b,m,d]  (A direct, B trans)
// Fused: denom (dot with g_ksum during A staging) + epilogue
//   out = num/denom + addproj + b_add   -> g_out
// ============================================================================
__global__ void __launch_bounds__(256) k_num_mma(const float* __restrict__ b_add)
{
    __shared__ __nv_bfloat16 sAhi[128 * TPAD], sAlo[128 * TPAD];  // qp [l][m-chunk]
    __shared__ __nv_bfloat16 sBhi[32 * KTP],   sBlo[32 * KTP];    // kv chunk [m][d]
    __shared__ float red2[128][4];

    const int d0 = blockIdx.x * 128;      // 0..1
    const int lt = blockIdx.y * 128;      // 0..15
    const int b  = blockIdx.z;
    const float* qpb = g_qp + (size_t)(b * LSEQ + lt) * TWOM;
    const float* kvb = g_kv + (size_t)b * TWOM * DM + d0;
    const float* ksb = g_ksum + b * TWOM;

    const int tid = threadIdx.x, wid = tid >> 5, lane = tid & 31;
    const int g8 = lane >> 3, r8 = lane & 7;
    const int wm = (wid >> 2) * 64, wn = (wid & 3) * 32;
    const int arow = wm + (lane & 15);
    const int akc  = (lane >> 4) * 8;

    float acc[4][4][4] = {};
    float dn[2] = {0.f, 0.f};

    const int srow0 = tid >> 2, scol8 = (tid & 3) * 8;    // A staging
    const int brow0 = tid >> 4, bcol8 = (tid & 15) * 8;   // B staging (rows 0..15, +16)

    for (int ch = 0; ch < TWOM / 32; ch++) {
        const int k0 = ch * 32;
#pragma unroll
        for (int i = 0; i < 2; i++) {
            int row = srow0 + i * 64;
            const float* p = qpb + (size_t)row * TWOM + k0 + scol8;
            float4 u = *(const float4*)p, v4 = *(const float4*)(p + 4);
            float xs[8] = {u.x, u.y, u.z, u.w, v4.x, v4.y, v4.z, v4.w};
            uint32_t hw[4], lw[4];
            cvt8(xs, hw, lw);
            const float* ks = ksb + k0 + scol8;
#pragma unroll
            for (int q = 0; q < 8; q++) dn[i] = fmaf(xs[q], ks[q], dn[i]);
            *(uint4*)(sAhi + row * TPAD + scol8) = make_uint4(hw[0], hw[1], hw[2], hw[3]);
            *(uint4*)(sAlo + row * TPAD + scol8) = make_uint4(lw[0], lw[1], lw[2], lw[3]);
        }
        // B tile: 32 k-rows x 128 d-cols = 4096 elems -> TWO passes of 2048
#pragma unroll
        for (int i = 0; i < 2; i++) {
            int row = brow0 + i * 16;
            stage8_cvt(kvb + (size_t)(k0 + row) * DM + bcol8, sBhi, sBlo, row * KTP + bcol8);
        }
        __syncthreads();

#pragma unroll
        for (int ks2 = 0; ks2 < 2; ks2++) {
            const int kc = ks2 * 16;
            uint32_t ahi[4][4], alo[4][4];
#pragma unroll
            for (int mi = 0; mi < 4; mi++) {
                const int off = (arow + mi * 16) * TPAD + kc + akc;
                ldmx4(ahi[mi], sAhi + off);
                ldmx4(alo[mi], sAlo + off);
            }
            uint32_t bhi[2][4], blo[2][4];
#pragma unroll
            for (int np = 0; np < 2; np++) {
                const int off = (kc + r8 + (g8 & 1) * 8) * KTP + wn + np * 16 + (g8 >> 1) * 8;
                ldmx4t(bhi[np], sBhi + off);
                ldmx4t(blo[np], sBlo + off);
            }
#pragma unroll
            for (int mi = 0; mi < 4; mi++)
#pragma unroll
                for (int nj = 0; nj < 4; nj++) {
                    const int np = nj >> 1, o = (nj & 1) * 2;
                    mma16816(acc[mi][nj], ahi[mi], bhi[np][o], bhi[np][o+1]);
                    mma16816(acc[mi][nj], ahi[mi], blo[np][o], blo[np][o+1]);
                    mma16816(acc[mi][nj], alo[mi], bhi[np][o], bhi[np][o+1]);
                }
        }
        __syncthreads();
    }

    red2[srow0][tid & 3]      = dn[0];
    red2[srow0 + 64][tid & 3] = dn[1];
    __syncthreads();

    const int rr0 = wm + (lane >> 2);
    const int cc0 = d0 + wn + (lane & 3) * 2;
#pragma unroll
    for (int mi = 0; mi < 4; mi++) {
#pragma unroll
        for (int h = 0; h < 2; h++) {
            int rloc = rr0 + mi * 16 + h * 8;
            float den = red2[rloc][0] + red2[rloc][1] + red2[rloc][2] + red2[rloc][3];
            float inv = 1.0f / den;
            int rg = b * LSEQ + lt + rloc;
            const float* addp = g_qkva + (size_t)rg * NPROJ + 3 * DM;
            float* orow = g_out + (size_t)rg * DM;
#pragma unroll
            for (int nj = 0; nj < 4; nj++) {
                int c = cc0 + nj * 8;
                float v0 = acc[mi][nj][h*2]   * inv + addp[c]     + b_add[c];
                float v1 = acc[mi][nj][h*2+1] * inv + addp[c + 1] + b_add[c + 1];
                *(float2*)&orow[c] = make_float2(v0, v1);
            }
        }
    }
}

// ============================================================================
// Kernel 6a: init d_out with b_final.
// ============================================================================
__global__ void k_init_out(float* __restrict__ out, const float* __restrict__ bf)
{
    int i = threadIdx.x;                 // 512 threads
    out[i] = bf[i & 63];
}

// ============================================================================
// Kernel 6b: result[b,c] += sum_f out[b,f] * Wf[c,f]   (split-K, atomics)
// ============================================================================
__global__ void __launch_bounds__(256) k_final(const float* __restrict__ Wf,
                                               float* __restrict__ out)
{
    __shared__ float Ws[64][130];
    __shared__ float Os[8][132];

    const int tid = threadIdx.x;
    const int c  = tid & 63;
    const int bb = tid >> 6;             // 0..3
    float acc0 = 0.f, acc1 = 0.f;
    const int f0 = blockIdx.x * 1024;

    for (int t = 0; t < 1024; t += 128) {
        const int fbase = f0 + t;
#pragma unroll
        for (int i = 0; i < 8; i++) {    // Ws: 2048 float4 / 256 thr
            int v = tid + i * 256;
            int cc = v >> 5, f4 = (v & 31) * 4;
            float4 w = *(const float4*)(Wf + (size_t)cc * FTOT + fbase + f4);
            Ws[cc][f4] = w.x; Ws[cc][f4+1] = w.y; Ws[cc][f4+2] = w.z; Ws[cc][f4+3] = w.w;
        }
        {                                // Os: 256 float4 / 256 thr
            int v = tid;
            int bo = v >> 5, f4 = (v & 31) * 4;
            float4 o = *(const float4*)(g_out + (size_t)bo * FTOT + fbase + f4);
            Os[bo][f4] = o.x; Os[bo][f4+1] = o.y; Os[bo][f4+2] = o.z; Os[bo][f4+3] = o.w;
        }
        __syncthreads();
#pragma unroll 8
        for (int fi = 0; fi < 128; fi++) {
            float w = Ws[c][fi];
            acc0 = fmaf(Os[bb][fi],     w, acc0);
            acc1 = fmaf(Os[bb + 4][fi], w, acc1);
        }
        __syncthreads();
    }
    atomicAdd(&out[bb * NCLASS + c],       acc0);
    atomicAdd(&out[(bb + 4) * NCLASS + c], acc1);
}

// ============================================================================
extern "C" void kernel_launch(void* const* d_in, const int* in_sizes, int n_in,
                              void* d_out, int out_size)
{
    const float* X  = (const float*)d_in[0];
    // d_in[1..6]: unused scalars
    const float* Wq = (const float*)d_in[7];
    const float* Wk = (const float*)d_in[8];
    const float* Wv = (const float*)d_in[9];
    const float* Wa = (const float*)d_in[10];
    const float* bA = (const float*)d_in[11];
    const float* Wf = (const float*)d_in[12];
    const float* bF = (const float*)d_in[13];
    const float* rf = (const float*)d_in[14];
    float* out = (float*)d_out;

    k_proj_mma<<<dim3(8, 128),    256>>>(X, Wq, Wk, Wv, Wa);
    k_rowscale<<<dim3(2048, 2),   256>>>();
    k_phi_mma <<<dim3(2, 128, 2), 256>>>(rf);
    k_kv_mma  <<<dim3(4, 4, 8),   256>>>();
    k_num_mma <<<dim3(2, 16, 8),  256>>>(bA);
    k_init_out<<<1, 512>>>(out, bF);
    k_final   <<<512, 256>>>(Wf, out);
}

// round 7
// speedup vs baseline: 1.6539x; 1.1311x over previous
#include <cuda_runtime.h>
#include <cuda_bf16.h>
#include <math.h>
#include <cstdint>

// Problem constants
#define NB     8
#define LSEQ   2048
#define BL     16384          // NB*LSEQ
#define DLEN   512
#define DM     256
#define NPROJ  1024           // Q|K|V|Add concatenated
#define MRF    256
#define TWOM   512
#define NCLASS 64
#define FTOT   (LSEQ*DM)      // 524288 flattened features per batch

#define TWO_PI 6.28318530717958647692f
#define LSPLIT 4              // L-splits for kv kernel

// ---------------- device scratch (allocation-free rule: static globals) ----
__device__ float g_qkva[BL * NPROJ];      // 64 MB : [row, 1024] = Q|K|V|Add
__device__ float g_scale_q[BL];
__device__ float g_scale_k[BL];
__device__ float g_qp[BL * TWOM];         // 32 MB
__device__ float g_kp[BL * TWOM];         // 32 MB
__device__ float g_ksum[NB * TWOM];
__device__ float g_kv[NB * TWOM * DM];    // 4 MB
__device__ float g_out[BL * DM];          // 16 MB (== [b, FTOT] flat)

// ============================================================================
// mma.sync helpers (baseline PTX — valid at compute_100, no 'a' features)
// ============================================================================
__device__ __forceinline__ uint32_t smem_u32(const void* p) {
    uint32_t a;
    asm("{ .reg .u64 t; cvta.to.shared.u64 t, %1; cvt.u32.u64 %0, t; }" : "=r"(a) : "l"(p));
    return a;
}

__device__ __forceinline__ void ldmx4(uint32_t r[4], const void* p) {
    uint32_t a = smem_u32(p);
    asm volatile("ldmatrix.sync.aligned.m8n8.x4.shared.b16 {%0,%1,%2,%3}, [%4];"
                 : "=r"(r[0]), "=r"(r[1]), "=r"(r[2]), "=r"(r[3]) : "r"(a));
}
__device__ __forceinline__ void ldmx4t(uint32_t r[4], const void* p) {
    uint32_t a = smem_u32(p);
    asm volatile("ldmatrix.sync.aligned.m8n8.x4.trans.shared.b16 {%0,%1,%2,%3}, [%4];"
                 : "=r"(r[0]), "=r"(r[1]), "=r"(r[2]), "=r"(r[3]) : "r"(a));
}

__device__ __forceinline__ void mma16816(float d[4], const uint32_t a[4],
                                         uint32_t b0, uint32_t b1) {
    asm volatile(
        "mma.sync.aligned.m16n8k16.row.col.f32.bf16.bf16.f32 "
        "{%0,%1,%2,%3}, {%4,%5,%6,%7}, {%8,%9}, {%0,%1,%2,%3};"
        : "+f"(d[0]), "+f"(d[1]), "+f"(d[2]), "+f"(d[3])
        : "r"(a[0]), "r"(a[1]), "r"(a[2]), "r"(a[3]), "r"(b0), "r"(b1));
}

// padded smem row strides (bf16 units) chosen so 8 consecutive rows hit
// distinct bank groups for (trans-)ldmatrix phases.
#define TPAD 40    // [row][32 k]  tiles (stride 40 -> step 20 banks)
#define KTP  136   // [32 k][128 c] tiles (stride 136 -> step 4 banks)
#define KTPB 72    // [32 k][64 c]  tiles (stride 72  -> step 4 banks)

__device__ __forceinline__ void cvt8(const float xs[8], uint32_t hw[4], uint32_t lw[4]) {
#pragma unroll
    for (int q = 0; q < 4; q++) {
        __nv_bfloat16 h0 = __float2bfloat16_rn(xs[2*q]);
        __nv_bfloat16 h1 = __float2bfloat16_rn(xs[2*q+1]);
        hw[q] = (uint32_t)__bfloat16_as_ushort(h0) | ((uint32_t)__bfloat16_as_ushort(h1) << 16);
        __nv_bfloat16 l0 = __float2bfloat16_rn(xs[2*q]   - __bfloat162float(h0));
        __nv_bfloat16 l1 = __float2bfloat16_rn(xs[2*q+1] - __bfloat162float(h1));
        lw[q] = (uint32_t)__bfloat16_as_ushort(l0) | ((uint32_t)__bfloat16_as_ushort(l1) << 16);
    }
}

__device__ __forceinline__ void stage8_cvt(const float* __restrict__ p,
                                           __nv_bfloat16* __restrict__ hi,
                                           __nv_bfloat16* __restrict__ lo,
                                           int idx) {
    float4 u = *(const float4*)p;
    float4 v = *(const float4*)(p + 4);
    float xs[8] = {u.x, u.y, u.z, u.w, v.x, v.y, v.z, v.w};
    uint32_t hw[4], lw[4];
    cvt8(xs, hw, lw);
    *(uint4*)(hi + idx) = make_uint4(hw[0], hw[1], hw[2], hw[3]);
    *(uint4*)(lo + idx) = make_uint4(lw[0], lw[1], lw[2], lw[3]);
}

// Core: C[128,128] (this block) = A[128,K] @ B[128,K]^T, bf16x3 compensated.
// Register-prefetch double buffered: chunk ch+1's gmem data is loaded into
// registers while chunk ch's MMAs run.
template<int KCH>   // number of 32-wide K chunks
__device__ __forceinline__ void gemm_core(const float* __restrict__ Asrc, int astr,
                                          const float* __restrict__ Bsrc, int bstr,
                                          float acc[4][4][4],
                                          __nv_bfloat16* sAhi, __nv_bfloat16* sAlo,
                                          __nv_bfloat16* sBhi, __nv_bfloat16* sBlo)
{
    const int tid = threadIdx.x;
    const int wid = tid >> 5, lane = tid & 31;
    const int wm = (wid >> 2) * 64;
    const int wn = (wid & 3) * 32;
    const int arow = wm + (lane & 15);
    const int akc  = (lane >> 4) * 8;
    const int brow = wn + (lane >> 4) * 8 + (lane & 7);
    const int bkc  = ((lane >> 3) & 1) * 8;

    const int srow = tid >> 2, soct8 = (tid & 3) * 8;   // staging coords

    float pa[2][8], pb[2][8];
    // prefetch chunk 0
#pragma unroll
    for (int i = 0; i < 2; i++) {
        const float* p = Asrc + (size_t)(srow + i * 64) * astr + soct8;
        *(float4*)&pa[i][0] = *(const float4*)p;
        *(float4*)&pa[i][4] = *(const float4*)(p + 4);
        const float* q = Bsrc + (size_t)(srow + i * 64) * bstr + soct8;
        *(float4*)&pb[i][0] = *(const float4*)q;
        *(float4*)&pb[i][4] = *(const float4*)(q + 4);
    }

    for (int ch = 0; ch < KCH; ch++) {
        // convert + store current chunk to smem
#pragma unroll
        for (int i = 0; i < 2; i++) {
            uint32_t hw[4], lw[4];
            cvt8(pa[i], hw, lw);
            int idx = (srow + i * 64) * TPAD + soct8;
            *(uint4*)(sAhi + idx) = make_uint4(hw[0], hw[1], hw[2], hw[3]);
            *(uint4*)(sAlo + idx) = make_uint4(lw[0], lw[1], lw[2], lw[3]);
            cvt8(pb[i], hw, lw);
            *(uint4*)(sBhi + idx) = make_uint4(hw[0], hw[1], hw[2], hw[3]);
            *(uint4*)(sBlo + idx) = make_uint4(lw[0], lw[1], lw[2], lw[3]);
        }
        __syncthreads();

        // prefetch next chunk (LDGs overlap with MMA section below)
        if (ch + 1 < KCH) {
            const int k1 = (ch + 1) * 32;
#pragma unroll
            for (int i = 0; i < 2; i++) {
                const float* p = Asrc + (size_t)(srow + i * 64) * astr + k1 + soct8;
                *(float4*)&pa[i][0] = *(const float4*)p;
                *(float4*)&pa[i][4] = *(const float4*)(p + 4);
                const float* q = Bsrc + (size_t)(srow + i * 64) * bstr + k1 + soct8;
                *(float4*)&pb[i][0] = *(const float4*)q;
                *(float4*)&pb[i][4] = *(const float4*)(q + 4);
            }
        }

#pragma unroll
        for (int ks = 0; ks < 2; ks++) {
            const int kc = ks * 16;
            uint32_t ahi[4][4], alo[4][4];
#pragma unroll
            for (int mi = 0; mi < 4; mi++) {
                const int off = (arow + mi * 16) * TPAD + kc + akc;
                ldmx4(ahi[mi], sAhi + off);
                ldmx4(alo[mi], sAlo + off);
            }
            uint32_t bhi[2][4], blo[2][4];
#pragma unroll
            for (int np = 0; np < 2; np++) {
                const int off = (brow + np * 16) * TPAD + kc + bkc;
                ldmx4(bhi[np], sBhi + off);
                ldmx4(blo[np], sBlo + off);
            }
#pragma unroll
            for (int mi = 0; mi < 4; mi++)
#pragma unroll
                for (int nj = 0; nj < 4; nj++) {
                    const int np = nj >> 1, o = (nj & 1) * 2;
                    mma16816(acc[mi][nj], ahi[mi], bhi[np][o], bhi[np][o+1]);
                    mma16816(acc[mi][nj], ahi[mi], blo[np][o], blo[np][o+1]);
                    mma16816(acc[mi][nj], alo[mi], bhi[np][o], bhi[np][o+1]);
                }
        }
        __syncthreads();
    }
}

// ============================================================================
// Kernel 0: zero kv + ksum accumulators (graph-replayed every launch)
// ============================================================================
__global__ void k_zero_acc()
{
    int idx = blockIdx.x * 256 + threadIdx.x;     // 1024 blocks
    ((float4*)g_kv)[idx] = make_float4(0.f, 0.f, 0.f, 0.f);
    if (idx < NB * TWOM / 4)
        ((float4*)g_ksum)[idx] = make_float4(0.f, 0.f, 0.f, 0.f);
}

// ============================================================================
// Kernel 1 (mma): qkva[row, n] = X[row,:] . Wcat[n,:]
// ============================================================================
__global__ void __launch_bounds__(256) k_proj_mma(const float* __restrict__ X,
                                                  const float* __restrict__ Wq,
                                                  const float* __restrict__ Wk,
                                                  const float* __restrict__ Wv,
                                                  const float* __restrict__ Wa)
{
    __shared__ __nv_bfloat16 sAhi[128 * TPAD], sAlo[128 * TPAD];
    __shared__ __nv_bfloat16 sBhi[128 * TPAD], sBlo[128 * TPAD];

    const int bn = blockIdx.x;            // 0..7
    const int bm = blockIdx.y;            // 0..127
    const int which = bn >> 1;
    const float* W = (which == 0) ? Wq : (which == 1) ? Wk : (which == 2) ? Wv : Wa;
    const float* Bsrc = W + (size_t)(bn & 1) * 128 * DLEN;
    const float* Asrc = X + (size_t)bm * 128 * DLEN;

    float acc[4][4][4] = {};
    gemm_core<16>(Asrc, DLEN, Bsrc, DLEN, acc, sAhi, sAlo, sBhi, sBlo);

    const int tid = threadIdx.x;
    const int wid = tid >> 5, lane = tid & 31;
    const int r0 = bm * 128 + (wid >> 2) * 64 + (lane >> 2);
    const int c0 = bn * 128 + (wid & 3) * 32 + (lane & 3) * 2;
#pragma unroll
    for (int mi = 0; mi < 4; mi++)
#pragma unroll
        for (int nj = 0; nj < 4; nj++) {
            int r = r0 + mi * 16, c = c0 + nj * 8;
            *(float2*)&g_qkva[(size_t)r * NPROJ + c]       = make_float2(acc[mi][nj][0], acc[mi][nj][1]);
            *(float2*)&g_qkva[(size_t)(r + 8) * NPROJ + c] = make_float2(acc[mi][nj][2], acc[mi][nj][3]);
        }
}

// ============================================================================
// Kernel 2: per-row scale = exp(0.5*||q||^2) / sqrt(M),  for Q and K halves.
// ============================================================================
__global__ void k_rowscale()
{
    int warp = (blockIdx.x * blockDim.x + threadIdx.x) >> 5;
    int lane = threadIdx.x & 31;
    int isK = blockIdx.y;
    if (warp >= BL) return;
    const float* row = g_qkva + (size_t)warp * NPROJ + (isK ? DM : 0);
    float s = 0.f;
#pragma unroll
    for (int i = lane; i < DM; i += 32) { float v = row[i]; s = fmaf(v, v, s); }
#pragma unroll
    for (int o = 16; o; o >>= 1) s += __shfl_xor_sync(0xFFFFFFFFu, s, o);
    if (lane == 0) {
        float sc = expf(0.5f * s) * 0.0625f;   // 1/sqrt(256) = 1/16
        (isK ? g_scale_k : g_scale_q)[warp] = sc;
    }
}

// ============================================================================
// Kernel 3 (mma): phi.  proj = (Q or K)[128,256] @ rf[128-tile,256]^T,
// epilogue sincos * rowscale -> qp/kp.
// ============================================================================
__global__ void __launch_bounds__(256) k_phi_mma(const float* __restrict__ rf)
{
    __shared__ __nv_bfloat16 sAhi[128 * TPAD], sAlo[128 * TPAD];
    __shared__ __nv_bfloat16 sBhi[128 * TPAD], sBlo[128 * TPAD];

    const int bn = blockIdx.x;            // 0..1
    const int bm = blockIdx.y;            // 0..127
    const int isK = blockIdx.z;
    const float* Asrc = g_qkva + (size_t)bm * 128 * NPROJ + (isK ? DM : 0);
    const float* Bsrc = rf + (size_t)bn * 128 * MRF;

    float acc[4][4][4] = {};
    gemm_core<8>(Asrc, NPROJ, Bsrc, MRF, acc, sAhi, sAlo, sBhi, sBlo);

    float* OUT = isK ? g_kp : g_qp;
    const float* SC = isK ? g_scale_k : g_scale_q;

    const int tid = threadIdx.x;
    const int wid = tid >> 5, lane = tid & 31;
    const int r0 = bm * 128 + (wid >> 2) * 64 + (lane >> 2);
    const int c0 = bn * 128 + (wid & 3) * 32 + (lane & 3) * 2;
#pragma unroll
    for (int mi = 0; mi < 4; mi++) {
        int r  = r0 + mi * 16;
        float sa = SC[r], sb = SC[r + 8];
        float* rowa = OUT + (size_t)r * TWOM;
        float* rowb = OUT + (size_t)(r + 8) * TWOM;
#pragma unroll
        for (int nj = 0; nj < 4; nj++) {
            int c = c0 + nj * 8;
            float s0, cz0, s1, cz1, s2, cz2, s3, cz3;
            sincosf(TWO_PI * acc[mi][nj][0], &s0, &cz0);
            sincosf(TWO_PI * acc[mi][nj][1], &s1, &cz1);
            sincosf(TWO_PI * acc[mi][nj][2], &s2, &cz2);
            sincosf(TWO_PI * acc[mi][nj][3], &s3, &cz3);
            *(float2*)&rowa[c]      = make_float2(s0 * sa,  s1 * sa);
            *(float2*)&rowa[c + DM] = make_float2(cz0 * sa, cz1 * sa);
            *(float2*)&rowb[c]      = make_float2(s2 * sb,  s3 * sb);
            *(float2*)&rowb[c + DM] = make_float2(cz2 * sb, cz3 * sb);
        }
    }
}

// ============================================================================
// Kernel 4 (mma): kv[b, m, d] += sum_{l in split} kp[b,l,m] * v[b,l,d]
// Split-L x4 for occupancy; atomic fp32 accumulation. Fused ksum (d-tile 0).
// ============================================================================
__global__ void __launch_bounds__(256) k_kv_mma()
{
    __shared__ __nv_bfloat16 sAhi[32 * KTP],  sAlo[32 * KTP];    // kp chunk [l][m]
    __shared__ __nv_bfloat16 sBhi[32 * KTPB], sBlo[32 * KTPB];   // v  chunk [l][d]
    __shared__ float red[16][128];

    const int d0 = blockIdx.x * 64;       // 0..3
    const int m0 = blockIdx.y * 128;      // 0..3
    const int b  = blockIdx.z >> 2;       // 0..7
    const int sp = blockIdx.z & 3;        // L-split 0..3
    const float* kpb = g_kp   + (size_t)b * LSEQ * TWOM  + m0;
    const float* vb  = g_qkva + (size_t)b * LSEQ * NPROJ + 2 * DM + d0;

    const int tid = threadIdx.x, wid = tid >> 5, lane = tid & 31;
    const int g8 = lane >> 3, r8 = lane & 7;
    const int wm = (wid >> 2) * 64, wn = (wid & 3) * 16;

    float acc[4][2][4] = {};
    float ksp[8] = {};

    const int arow0 = tid >> 4, acol8 = (tid & 15) * 8;   // A staging slots
    const int brow0 = tid >> 3, bcol8 = (tid & 7) * 8;    // B staging slot

    const int ch0 = sp * (LSEQ / 32 / LSPLIT);
    const int ch1 = ch0 + (LSEQ / 32 / LSPLIT);
    for (int ch = ch0; ch < ch1; ch++) {
        const int l0 = ch * 32;
#pragma unroll
        for (int i = 0; i < 2; i++) {
            int row = arow0 + i * 16;
            const float* p = kpb + (size_t)(l0 + row) * TWOM + acol8;
            float4 u = *(const float4*)p, v4 = *(const float4*)(p + 4);
            float xs[8] = {u.x, u.y, u.z, u.w, v4.x, v4.y, v4.z, v4.w};
            uint32_t hw[4], lw[4];
            cvt8(xs, hw, lw);
#pragma unroll
            for (int q = 0; q < 8; q++) ksp[q] += xs[q];
            *(uint4*)(sAhi + row * KTP + acol8) = make_uint4(hw[0], hw[1], hw[2], hw[3]);
            *(uint4*)(sAlo + row * KTP + acol8) = make_uint4(lw[0], lw[1], lw[2], lw[3]);
        }
        stage8_cvt(vb + (size_t)(l0 + brow0) * NPROJ + bcol8, sBhi, sBlo, brow0 * KTPB + bcol8);
        __syncthreads();

#pragma unroll
        for (int ks = 0; ks < 2; ks++) {
            const int kc = ks * 16;
            uint32_t ahi[4][4], alo[4][4];
#pragma unroll
            for (int mi = 0; mi < 4; mi++) {
                const int off = (kc + r8 + (g8 >> 1) * 8) * KTP + wm + mi * 16 + (g8 & 1) * 8;
                ldmx4t(ahi[mi], sAhi + off);
                ldmx4t(alo[mi], sAlo + off);
            }
            uint32_t bhi[4], blo[4];
            {
                const int off = (kc + r8 + (g8 & 1) * 8) * KTPB + wn + (g8 >> 1) * 8;
                ldmx4t(bhi, sBhi + off);
                ldmx4t(blo, sBlo + off);
            }
#pragma unroll
            for (int mi = 0; mi < 4; mi++)
#pragma unroll
                for (int nj = 0; nj < 2; nj++) {
                    const int o = nj * 2;
                    mma16816(acc[mi][nj], ahi[mi], bhi[o], bhi[o+1]);
                    mma16816(acc[mi][nj], ahi[mi], blo[o], blo[o+1]);
                    mma16816(acc[mi][nj], alo[mi], bhi[o], bhi[o+1]);
                }
        }
        __syncthreads();
    }

    const int rr0 = m0 + wm + (lane >> 2);
    const int cc0 = d0 + wn + (lane & 3) * 2;
#pragma unroll
    for (int mi = 0; mi < 4; mi++)
#pragma unroll
        for (int nj = 0; nj < 2; nj++) {
            int r = rr0 + mi * 16, c = cc0 + nj * 8;
            float* p0 = &g_kv[((size_t)b * TWOM + r) * DM + c];
            float* p1 = &g_kv[((size_t)b * TWOM + r + 8) * DM + c];
            atomicAdd(p0,     acc[mi][nj][0]);
            atomicAdd(p0 + 1, acc[mi][nj][1]);
            atomicAdd(p1,     acc[mi][nj][2]);
            atomicAdd(p1 + 1, acc[mi][nj][3]);
        }

    if (blockIdx.x == 0) {   // fused ksum partial for this m-tile / L-split
#pragma unroll
        for (int q = 0; q < 8; q++) red[arow0][acol8 + q] = ksp[q];
        __syncthreads();
        if (tid < 128) {
            float s = 0.f;
#pragma unroll
            for (int j = 0; j < 16; j++) s += red[j][tid];
            atomicAdd(&g_ksum[b * TWOM + m0 + tid], s);
        }
    }
}

// ============================================================================
// Kernel 5 (mma): num[b,l,d] = sum_m qp[b,l,m] * kv[b,m,d]  (A direct, B trans)
// Fused: denom (dot with g_ksum during A staging) + epilogue
//   out = num/denom + addproj + b_add   -> g_out
// ============================================================================
__global__ void __launch_bounds__(256) k_num_mma(const float* __restrict__ b_add)
{
    __shared__ __nv_bfloat16 sAhi[128 * TPAD], sAlo[128 * TPAD];  // qp [l][m-chunk]
    __shared__ __nv_bfloat16 sBhi[32 * KTP],   sBlo[32 * KTP];    // kv chunk [m][d]
    __shared__ float red2[128][4];

    const int d0 = blockIdx.x * 128;      // 0..1
    const int lt = blockIdx.y * 128;      // 0..15
    const int b  = blockIdx.z;
    const float* qpb = g_qp + (size_t)(b * LSEQ + lt) * TWOM;
    const float* kvb = g_kv + (size_t)b * TWOM * DM + d0;
    const float* ksb = g_ksum + b * TWOM;

    const int tid = threadIdx.x, wid = tid >> 5, lane = tid & 31;
    const int g8 = lane >> 3, r8 = lane & 7;
    const int wm = (wid >> 2) * 64, wn = (wid & 3) * 32;
    const int arow = wm + (lane & 15);
    const int akc  = (lane >> 4) * 8;

    float acc[4][4][4] = {};
    float dn[2] = {0.f, 0.f};

    const int srow0 = tid >> 2, scol8 = (tid & 3) * 8;    // A staging
    const int brow0 = tid >> 4, bcol8 = (tid & 15) * 8;   // B staging (rows 0..15, +16)

    for (int ch = 0; ch < TWOM / 32; ch++) {
        const int k0 = ch * 32;
#pragma unroll
        for (int i = 0; i < 2; i++) {
            int row = srow0 + i * 64;
            const float* p = qpb + (size_t)row * TWOM + k0 + scol8;
            float4 u = *(const float4*)p, v4 = *(const float4*)(p + 4);
            float xs[8] = {u.x, u.y, u.z, u.w, v4.x, v4.y, v4.z, v4.w};
            uint32_t hw[4], lw[4];
            cvt8(xs, hw, lw);
            const float* ks = ksb + k0 + scol8;
#pragma unroll
            for (int q = 0; q < 8; q++) dn[i] = fmaf(xs[q], ks[q], dn[i]);
            *(uint4*)(sAhi + row * TPAD + scol8) = make_uint4(hw[0], hw[1], hw[2], hw[3]);
            *(uint4*)(sAlo + row * TPAD + scol8) = make_uint4(lw[0], lw[1], lw[2], lw[3]);
        }
        // B tile: 32 k-rows x 128 d-cols = 4096 elems -> TWO passes of 2048
#pragma unroll
        for (int i = 0; i < 2; i++) {
            int row = brow0 + i * 16;
            stage8_cvt(kvb + (size_t)(k0 + row) * DM + bcol8, sBhi, sBlo, row * KTP + bcol8);
        }
        __syncthreads();

#pragma unroll
        for (int ks2 = 0; ks2 < 2; ks2++) {
            const int kc = ks2 * 16;
            uint32_t ahi[4][4], alo[4][4];
#pragma unroll
            for (int mi = 0; mi < 4; mi++) {
                const int off = (arow + mi * 16) * TPAD + kc + akc;
                ldmx4(ahi[mi], sAhi + off);
                ldmx4(alo[mi], sAlo + off);
            }
            uint32_t bhi[2][4], blo[2][4];
#pragma unroll
            for (int np = 0; np < 2; np++) {
                const int off = (kc + r8 + (g8 & 1) * 8) * KTP + wn + np * 16 + (g8 >> 1) * 8;
                ldmx4t(bhi[np], sBhi + off);
                ldmx4t(blo[np], sBlo + off);
            }
#pragma unroll
            for (int mi = 0; mi < 4; mi++)
#pragma unroll
                for (int nj = 0; nj < 4; nj++) {
                    const int np = nj >> 1, o = (nj & 1) * 2;
                    mma16816(acc[mi][nj], ahi[mi], bhi[np][o], bhi[np][o+1]);
                    mma16816(acc[mi][nj], ahi[mi], blo[np][o], blo[np][o+1]);
                    mma16816(acc[mi][nj], alo[mi], bhi[np][o], bhi[np][o+1]);
                }
        }
        __syncthreads();
    }

    red2[srow0][tid & 3]      = dn[0];
    red2[srow0 + 64][tid & 3] = dn[1];
    __syncthreads();

    const int rr0 = wm + (lane >> 2);
    const int cc0 = d0 + wn + (lane & 3) * 2;
#pragma unroll
    for (int mi = 0; mi < 4; mi++) {
#pragma unroll
        for (int h = 0; h < 2; h++) {
            int rloc = rr0 + mi * 16 + h * 8;
            float den = red2[rloc][0] + red2[rloc][1] + red2[rloc][2] + red2[rloc][3];
            float inv = 1.0f / den;
            int rg = b * LSEQ + lt + rloc;
            const float* addp = g_qkva + (size_t)rg * NPROJ + 3 * DM;
            float* orow = g_out + (size_t)rg * DM;
#pragma unroll
            for (int nj = 0; nj < 4; nj++) {
                int c = cc0 + nj * 8;
                float v0 = acc[mi][nj][h*2]   * inv + addp[c]     + b_add[c];
                float v1 = acc[mi][nj][h*2+1] * inv + addp[c + 1] + b_add[c + 1];
                *(float2*)&orow[c] = make_float2(v0, v1);
            }
        }
    }
}

// ============================================================================
// Kernel 6a: init d_out with b_final.
// ============================================================================
__global__ void k_init_out(float* __restrict__ out, const float* __restrict__ bf)
{
    int i = threadIdx.x;                 // 512 threads
    out[i] = bf[i & 63];
}

// ============================================================================
// Kernel 6b: result[b,c] += sum_f out[b,f] * Wf[c,f]   (split-K, atomics)
// ============================================================================
__global__ void __launch_bounds__(256) k_final(const float* __restrict__ Wf,
                                               float* __restrict__ out)
{
    __shared__ float Ws[64][130];
    __shared__ float Os[8][132];

    const int tid = threadIdx.x;
    const int c  = tid & 63;
    const int bb = tid >> 6;             // 0..3
    float acc0 = 0.f, acc1 = 0.f;
    const int f0 = blockIdx.x * 1024;

    for (int t = 0; t < 1024; t += 128) {
        const int fbase = f0 + t;
#pragma unroll
        for (int i = 0; i < 8; i++) {    // Ws: 2048 float4 / 256 thr
            int v = tid + i * 256;
            int cc = v >> 5, f4 = (v & 31) * 4;
            float4 w = *(const float4*)(Wf + (size_t)cc * FTOT + fbase + f4);
            Ws[cc][f4] = w.x; Ws[cc][f4+1] = w.y; Ws[cc][f4+2] = w.z; Ws[cc][f4+3] = w.w;
        }
        {                                // Os: 256 float4 / 256 thr
            int v = tid;
            int bo = v >> 5, f4 = (v & 31) * 4;
            float4 o = *(const float4*)(g_out + (size_t)bo * FTOT + fbase + f4);
            Os[bo][f4] = o.x; Os[bo][f4+1] = o.y; Os[bo][f4+2] = o.z; Os[bo][f4+3] = o.w;
        }
        __syncthreads();
#pragma unroll 8
        for (int fi = 0; fi < 128; fi++) {
            float w = Ws[c][fi];
            acc0 = fmaf(Os[bb][fi],     w, acc0);
            acc1 = fmaf(Os[bb + 4][fi], w, acc1);
        }
        __syncthreads();
    }
    atomicAdd(&out[bb * NCLASS + c],       acc0);
    atomicAdd(&out[(bb + 4) * NCLASS + c], acc1);
}

// ============================================================================
extern "C" void kernel_launch(void* const* d_in, const int* in_sizes, int n_in,
                              void* d_out, int out_size)
{
    const float* X  = (const float*)d_in[0];
    // d_in[1..6]: unused scalars
    const float* Wq = (const float*)d_in[7];
    const float* Wk = (const float*)d_in[8];
    const float* Wv = (const float*)d_in[9];
    const float* Wa = (const float*)d_in[10];
    const float* bA = (const float*)d_in[11];
    const float* Wf = (const float*)d_in[12];
    const float* bF = (const float*)d_in[13];
    const float* rf = (const float*)d_in[14];
    float* out = (float*)d_out;

    k_zero_acc<<<1024,            256>>>();
    k_proj_mma<<<dim3(8, 128),    256>>>(X, Wq, Wk, Wv, Wa);
    k_rowscale<<<dim3(2048, 2),   256>>>();
    k_phi_mma <<<dim3(2, 128, 2), 256>>>(rf);
    k_kv_mma  <<<dim3(4, 4, 8 * LSPLIT), 256>>>();
    k_num_mma <<<dim3(2, 16, 8),  256>>>(bA);
    k_init_out<<<1, 512>>>(out, bF);
    k_final   <<<512, 256>>>(Wf, out);
}

// round 8
// speedup vs baseline: 1.9102x; 1.1550x over previous
#include <cuda_runtime.h>
#include <cuda_bf16.h>
#include <math.h>
#include <cstdint>

// Problem constants
#define NB     8
#define LSEQ   2048
#define BL     16384          // NB*LSEQ
#define DLEN   512
#define DM     256
#define NPROJ  1024           // Q|K|V|Add concatenated
#define MRF    256
#define TWOM   512
#define NCLASS 64
#define FTOT   (LSEQ*DM)      // 524288 flattened features per batch

#define TWO_PI 6.28318530717958647692f
#define LSPLIT 4              // L-splits for kv kernel

// ---------------- device scratch (allocation-free rule: static globals) ----
__device__ float g_qkva[BL * NPROJ];      // 64 MB : [row, 1024] = Q|K|V|Add
__device__ float g_scale_q[BL];
__device__ float g_scale_k[BL];
__device__ float g_qp[BL * TWOM];         // 32 MB
__device__ float g_kp[BL * TWOM];         // 32 MB
__device__ float g_ksum[NB * TWOM];
__device__ float g_kv[NB * TWOM * DM];    // 4 MB
__device__ float g_out[BL * DM];          // 16 MB (== [b, FTOT] flat)

// ============================================================================
// mma.sync helpers (baseline PTX — valid at compute_100, no 'a' features)
// ============================================================================
__device__ __forceinline__ uint32_t smem_u32(const void* p) {
    uint32_t a;
    asm("{ .reg .u64 t; cvta.to.shared.u64 t, %1; cvt.u32.u64 %0, t; }" : "=r"(a) : "l"(p));
    return a;
}

__device__ __forceinline__ void ldmx4(uint32_t r[4], const void* p) {
    uint32_t a = smem_u32(p);
    asm volatile("ldmatrix.sync.aligned.m8n8.x4.shared.b16 {%0,%1,%2,%3}, [%4];"
                 : "=r"(r[0]), "=r"(r[1]), "=r"(r[2]), "=r"(r[3]) : "r"(a));
}
__device__ __forceinline__ void ldmx4t(uint32_t r[4], const void* p) {
    uint32_t a = smem_u32(p);
    asm volatile("ldmatrix.sync.aligned.m8n8.x4.trans.shared.b16 {%0,%1,%2,%3}, [%4];"
                 : "=r"(r[0]), "=r"(r[1]), "=r"(r[2]), "=r"(r[3]) : "r"(a));
}

__device__ __forceinline__ void mma16816(float d[4], const uint32_t a[4],
                                         uint32_t b0, uint32_t b1) {
    asm volatile(
        "mma.sync.aligned.m16n8k16.row.col.f32.bf16.bf16.f32 "
        "{%0,%1,%2,%3}, {%4,%5,%6,%7}, {%8,%9}, {%0,%1,%2,%3};"
        : "+f"(d[0]), "+f"(d[1]), "+f"(d[2]), "+f"(d[3])
        : "r"(a[0]), "r"(a[1]), "r"(a[2]), "r"(a[3]), "r"(b0), "r"(b1));
}

// padded smem row strides (bf16 units) chosen so 8 consecutive rows hit
// distinct bank groups for (trans-)ldmatrix phases.
#define TPAD 40    // [row][32 k]  tiles (stride 40 -> step 20 banks)
#define KTP  136   // [32 k][128 c] tiles (stride 136 -> step 4 banks)
#define KTPB 72    // [32 k][64 c]  tiles (stride 72  -> step 4 banks)

__device__ __forceinline__ void cvt8(const float xs[8], uint32_t hw[4], uint32_t lw[4]) {
#pragma unroll
    for (int q = 0; q < 4; q++) {
        __nv_bfloat16 h0 = __float2bfloat16_rn(xs[2*q]);
        __nv_bfloat16 h1 = __float2bfloat16_rn(xs[2*q+1]);
        hw[q] = (uint32_t)__bfloat16_as_ushort(h0) | ((uint32_t)__bfloat16_as_ushort(h1) << 16);
        __nv_bfloat16 l0 = __float2bfloat16_rn(xs[2*q]   - __bfloat162float(h0));
        __nv_bfloat16 l1 = __float2bfloat16_rn(xs[2*q+1] - __bfloat162float(h1));
        lw[q] = (uint32_t)__bfloat16_as_ushort(l0) | ((uint32_t)__bfloat16_as_ushort(l1) << 16);
    }
}

__device__ __forceinline__ void stage8_cvt(const float* __restrict__ p,
                                           __nv_bfloat16* __restrict__ hi,
                                           __nv_bfloat16* __restrict__ lo,
                                           int idx) {
    float4 u = *(const float4*)p;
    float4 v = *(const float4*)(p + 4);
    float xs[8] = {u.x, u.y, u.z, u.w, v.x, v.y, v.z, v.w};
    uint32_t hw[4], lw[4];
    cvt8(xs, hw, lw);
    *(uint4*)(hi + idx) = make_uint4(hw[0], hw[1], hw[2], hw[3]);
    *(uint4*)(lo + idx) = make_uint4(lw[0], lw[1], lw[2], lw[3]);
}

// Core: C[128,64] (this block) = A[128,K] @ B[64,K]^T, bf16x3 compensated.
// acc[mi][nj]: warp (wid>>2)*64 + mi*16 rows, (wid&3)*16 + nj*8 cols.
// Register-prefetch double buffered; 2 CTAs/SM (acc halved vs 128x128).
template<int KCH>   // number of 32-wide K chunks
__device__ __forceinline__ void gemm_core64(const float* __restrict__ Asrc, int astr,
                                            const float* __restrict__ Bsrc, int bstr,
                                            float acc[4][2][4],
                                            __nv_bfloat16* sAhi, __nv_bfloat16* sAlo,
                                            __nv_bfloat16* sBhi, __nv_bfloat16* sBlo)
{
    const int tid = threadIdx.x;
    const int wid = tid >> 5, lane = tid & 31;
    const int wm = (wid >> 2) * 64;
    const int wn = (wid & 3) * 16;
    const int arow = wm + (lane & 15);
    const int akc  = (lane >> 4) * 8;
    const int brow = wn + (lane >> 4) * 8 + (lane & 7);
    const int bkc  = ((lane >> 3) & 1) * 8;

    const int srow = tid >> 2, soct8 = (tid & 3) * 8;   // staging coords

    float pa[2][8], pb[8];
    // prefetch chunk 0
#pragma unroll
    for (int i = 0; i < 2; i++) {
        const float* p = Asrc + (size_t)(srow + i * 64) * astr + soct8;
        *(float4*)&pa[i][0] = *(const float4*)p;
        *(float4*)&pa[i][4] = *(const float4*)(p + 4);
    }
    {
        const float* q = Bsrc + (size_t)srow * bstr + soct8;
        *(float4*)&pb[0] = *(const float4*)q;
        *(float4*)&pb[4] = *(const float4*)(q + 4);
    }

    for (int ch = 0; ch < KCH; ch++) {
        // convert + store current chunk to smem
#pragma unroll
        for (int i = 0; i < 2; i++) {
            uint32_t hw[4], lw[4];
            cvt8(pa[i], hw, lw);
            int idx = (srow + i * 64) * TPAD + soct8;
            *(uint4*)(sAhi + idx) = make_uint4(hw[0], hw[1], hw[2], hw[3]);
            *(uint4*)(sAlo + idx) = make_uint4(lw[0], lw[1], lw[2], lw[3]);
        }
        {
            uint32_t hw[4], lw[4];
            cvt8(pb, hw, lw);
            int idx = srow * TPAD + soct8;
            *(uint4*)(sBhi + idx) = make_uint4(hw[0], hw[1], hw[2], hw[3]);
            *(uint4*)(sBlo + idx) = make_uint4(lw[0], lw[1], lw[2], lw[3]);
        }
        __syncthreads();

        // prefetch next chunk (LDGs overlap with MMA section below)
        if (ch + 1 < KCH) {
            const int k1 = (ch + 1) * 32;
#pragma unroll
            for (int i = 0; i < 2; i++) {
                const float* p = Asrc + (size_t)(srow + i * 64) * astr + k1 + soct8;
                *(float4*)&pa[i][0] = *(const float4*)p;
                *(float4*)&pa[i][4] = *(const float4*)(p + 4);
            }
            const float* q = Bsrc + (size_t)srow * bstr + k1 + soct8;
            *(float4*)&pb[0] = *(const float4*)q;
            *(float4*)&pb[4] = *(const float4*)(q + 4);
        }

#pragma unroll
        for (int ks = 0; ks < 2; ks++) {
            const int kc = ks * 16;
            uint32_t ahi[4][4], alo[4][4];
#pragma unroll
            for (int mi = 0; mi < 4; mi++) {
                const int off = (arow + mi * 16) * TPAD + kc + akc;
                ldmx4(ahi[mi], sAhi + off);
                ldmx4(alo[mi], sAlo + off);
            }
            uint32_t bhi[4], blo[4];
            {
                const int off = brow * TPAD + kc + bkc;
                ldmx4(bhi, sBhi + off);
                ldmx4(blo, sBlo + off);
            }
#pragma unroll
            for (int mi = 0; mi < 4; mi++)
#pragma unroll
                for (int nj = 0; nj < 2; nj++) {
                    const int o = nj * 2;
                    mma16816(acc[mi][nj], ahi[mi], bhi[o], bhi[o+1]);
                    mma16816(acc[mi][nj], ahi[mi], blo[o], blo[o+1]);
                    mma16816(acc[mi][nj], alo[mi], bhi[o], bhi[o+1]);
                }
        }
        __syncthreads();
    }
}

// ============================================================================
// Kernel 0: zero kv + ksum accumulators (graph-replayed every launch)
// ============================================================================
__global__ void k_zero_acc()
{
    int idx = blockIdx.x * 256 + threadIdx.x;     // 1024 blocks
    ((float4*)g_kv)[idx] = make_float4(0.f, 0.f, 0.f, 0.f);
    if (idx < NB * TWOM / 4)
        ((float4*)g_ksum)[idx] = make_float4(0.f, 0.f, 0.f, 0.f);
}

// ============================================================================
// Kernel 1 (mma): qkva[row, n] = X[row,:] . Wcat[n,:]   (tiles 128m x 64n)
// ============================================================================
__global__ void __launch_bounds__(256, 2) k_proj_mma(const float* __restrict__ X,
                                                     const float* __restrict__ Wq,
                                                     const float* __restrict__ Wk,
                                                     const float* __restrict__ Wv,
                                                     const float* __restrict__ Wa)
{
    __shared__ __nv_bfloat16 sAhi[128 * TPAD], sAlo[128 * TPAD];
    __shared__ __nv_bfloat16 sBhi[64 * TPAD],  sBlo[64 * TPAD];

    const int bn = blockIdx.x;            // 0..15 (64-wide n tiles)
    const int bm = blockIdx.y;            // 0..127
    const int which = bn >> 2;
    const float* W = (which == 0) ? Wq : (which == 1) ? Wk : (which == 2) ? Wv : Wa;
    const float* Bsrc = W + (size_t)(bn & 3) * 64 * DLEN;
    const float* Asrc = X + (size_t)bm * 128 * DLEN;

    float acc[4][2][4] = {};
    gemm_core64<16>(Asrc, DLEN, Bsrc, DLEN, acc, sAhi, sAlo, sBhi, sBlo);

    const int tid = threadIdx.x;
    const int wid = tid >> 5, lane = tid & 31;
    const int r0 = bm * 128 + (wid >> 2) * 64 + (lane >> 2);
    const int c0 = bn * 64 + (wid & 3) * 16 + (lane & 3) * 2;
#pragma unroll
    for (int mi = 0; mi < 4; mi++)
#pragma unroll
        for (int nj = 0; nj < 2; nj++) {
            int r = r0 + mi * 16, c = c0 + nj * 8;
            *(float2*)&g_qkva[(size_t)r * NPROJ + c]       = make_float2(acc[mi][nj][0], acc[mi][nj][1]);
            *(float2*)&g_qkva[(size_t)(r + 8) * NPROJ + c] = make_float2(acc[mi][nj][2], acc[mi][nj][3]);
        }
}

// ============================================================================
// Kernel 2: per-row scale = exp(0.5*||q||^2) / sqrt(M),  for Q and K halves.
// ============================================================================
__global__ void k_rowscale()
{
    int warp = (blockIdx.x * blockDim.x + threadIdx.x) >> 5;
    int lane = threadIdx.x & 31;
    int isK = blockIdx.y;
    if (warp >= BL) return;
    const float* row = g_qkva + (size_t)warp * NPROJ + (isK ? DM : 0);
    float s = 0.f;
#pragma unroll
    for (int i = lane; i < DM; i += 32) { float v = row[i]; s = fmaf(v, v, s); }
#pragma unroll
    for (int o = 16; o; o >>= 1) s += __shfl_xor_sync(0xFFFFFFFFu, s, o);
    if (lane == 0) {
        float sc = expf(0.5f * s) * 0.0625f;   // 1/sqrt(256) = 1/16
        (isK ? g_scale_k : g_scale_q)[warp] = sc;
    }
}

// ============================================================================
// Kernel 3 (mma): phi.  proj = (Q or K)[128,256] @ rf[64-tile,256]^T,
// epilogue sincos * rowscale -> qp/kp.
// ============================================================================
__global__ void __launch_bounds__(256, 2) k_phi_mma(const float* __restrict__ rf)
{
    __shared__ __nv_bfloat16 sAhi[128 * TPAD], sAlo[128 * TPAD];
    __shared__ __nv_bfloat16 sBhi[64 * TPAD],  sBlo[64 * TPAD];

    const int bn = blockIdx.x;            // 0..3 (64-wide feature tiles)
    const int bm = blockIdx.y;            // 0..127
    const int isK = blockIdx.z;
    const float* Asrc = g_qkva + (size_t)bm * 128 * NPROJ + (isK ? DM : 0);
    const float* Bsrc = rf + (size_t)bn * 64 * MRF;

    float acc[4][2][4] = {};
    gemm_core64<8>(Asrc, NPROJ, Bsrc, MRF, acc, sAhi, sAlo, sBhi, sBlo);

    float* OUT = isK ? g_kp : g_qp;
    const float* SC = isK ? g_scale_k : g_scale_q;

    const int tid = threadIdx.x;
    const int wid = tid >> 5, lane = tid & 31;
    const int r0 = bm * 128 + (wid >> 2) * 64 + (lane >> 2);
    const int c0 = bn * 64 + (wid & 3) * 16 + (lane & 3) * 2;
#pragma unroll
    for (int mi = 0; mi < 4; mi++) {
        int r  = r0 + mi * 16;
        float sa = SC[r], sb = SC[r + 8];
        float* rowa = OUT + (size_t)r * TWOM;
        float* rowb = OUT + (size_t)(r + 8) * TWOM;
#pragma unroll
        for (int nj = 0; nj < 2; nj++) {
            int c = c0 + nj * 8;
            float s0, cz0, s1, cz1, s2, cz2, s3, cz3;
            sincosf(TWO_PI * acc[mi][nj][0], &s0, &cz0);
            sincosf(TWO_PI * acc[mi][nj][1], &s1, &cz1);
            sincosf(TWO_PI * acc[mi][nj][2], &s2, &cz2);
            sincosf(TWO_PI * acc[mi][nj][3], &s3, &cz3);
            *(float2*)&rowa[c]      = make_float2(s0 * sa,  s1 * sa);
            *(float2*)&rowa[c + DM] = make_float2(cz0 * sa, cz1 * sa);
            *(float2*)&rowb[c]      = make_float2(s2 * sb,  s3 * sb);
            *(float2*)&rowb[c + DM] = make_float2(cz2 * sb, cz3 * sb);
        }
    }
}

// ============================================================================
// Kernel 4 (mma): kv[b, m, d] += sum_{l in split} kp[b,l,m] * v[b,l,d]
// Split-L x4 for occupancy; atomic fp32 accumulation. Fused ksum (d-tile 0).
// ============================================================================
__global__ void __launch_bounds__(256, 2) k_kv_mma()
{
    __shared__ __nv_bfloat16 sAhi[32 * KTP],  sAlo[32 * KTP];    // kp chunk [l][m]
    __shared__ __nv_bfloat16 sBhi[32 * KTPB], sBlo[32 * KTPB];   // v  chunk [l][d]
    __shared__ float red[16][128];

    const int d0 = blockIdx.x * 64;       // 0..3
    const int m0 = blockIdx.y * 128;      // 0..3
    const int b  = blockIdx.z >> 2;       // 0..7
    const int sp = blockIdx.z & 3;        // L-split 0..3
    const float* kpb = g_kp   + (size_t)b * LSEQ * TWOM  + m0;
    const float* vb  = g_qkva + (size_t)b * LSEQ * NPROJ + 2 * DM + d0;

    const int tid = threadIdx.x, wid = tid >> 5, lane = tid & 31;
    const int g8 = lane >> 3, r8 = lane & 7;
    const int wm = (wid >> 2) * 64, wn = (wid & 3) * 16;

    float acc[4][2][4] = {};
    float ksp[8] = {};

    const int arow0 = tid >> 4, acol8 = (tid & 15) * 8;   // A staging slots
    const int brow0 = tid >> 3, bcol8 = (tid & 7) * 8;    // B staging slot

    const int ch0 = sp * (LSEQ / 32 / LSPLIT);
    const int ch1 = ch0 + (LSEQ / 32 / LSPLIT);
    for (int ch = ch0; ch < ch1; ch++) {
        const int l0 = ch * 32;
#pragma unroll
        for (int i = 0; i < 2; i++) {
            int row = arow0 + i * 16;
            const float* p = kpb + (size_t)(l0 + row) * TWOM + acol8;
            float4 u = *(const float4*)p, v4 = *(const float4*)(p + 4);
            float xs[8] = {u.x, u.y, u.z, u.w, v4.x, v4.y, v4.z, v4.w};
            uint32_t hw[4], lw[4];
            cvt8(xs, hw, lw);
#pragma unroll
            for (int q = 0; q < 8; q++) ksp[q] += xs[q];
            *(uint4*)(sAhi + row * KTP + acol8) = make_uint4(hw[0], hw[1], hw[2], hw[3]);
            *(uint4*)(sAlo + row * KTP + acol8) = make_uint4(lw[0], lw[1], lw[2], lw[3]);
        }
        stage8_cvt(vb + (size_t)(l0 + brow0) * NPROJ + bcol8, sBhi, sBlo, brow0 * KTPB + bcol8);
        __syncthreads();

#pragma unroll
        for (int ks = 0; ks < 2; ks++) {
            const int kc = ks * 16;
            uint32_t ahi[4][4], alo[4][4];
#pragma unroll
            for (int mi = 0; mi < 4; mi++) {
                const int off = (kc + r8 + (g8 >> 1) * 8) * KTP + wm + mi * 16 + (g8 & 1) * 8;
                ldmx4t(ahi[mi], sAhi + off);
                ldmx4t(alo[mi], sAlo + off);
            }
            uint32_t bhi[4], blo[4];
            {
                const int off = (kc + r8 + (g8 & 1) * 8) * KTPB + wn + (g8 >> 1) * 8;
                ldmx4t(bhi, sBhi + off);
                ldmx4t(blo, sBlo + off);
            }
#pragma unroll
            for (int mi = 0; mi < 4; mi++)
#pragma unroll
                for (int nj = 0; nj < 2; nj++) {
                    const int o = nj * 2;
                    mma16816(acc[mi][nj], ahi[mi], bhi[o], bhi[o+1]);
                    mma16816(acc[mi][nj], ahi[mi], blo[o], blo[o+1]);
                    mma16816(acc[mi][nj], alo[mi], bhi[o], bhi[o+1]);
                }
        }
        __syncthreads();
    }

    const int rr0 = m0 + wm + (lane >> 2);
    const int cc0 = d0 + wn + (lane & 3) * 2;
#pragma unroll
    for (int mi = 0; mi < 4; mi++)
#pragma unroll
        for (int nj = 0; nj < 2; nj++) {
            int r = rr0 + mi * 16, c = cc0 + nj * 8;
            float* p0 = &g_kv[((size_t)b * TWOM + r) * DM + c];
            float* p1 = &g_kv[((size_t)b * TWOM + r + 8) * DM + c];
            atomicAdd(p0,     acc[mi][nj][0]);
            atomicAdd(p0 + 1, acc[mi][nj][1]);
            atomicAdd(p1,     acc[mi][nj][2]);
            atomicAdd(p1 + 1, acc[mi][nj][3]);
        }

    if (blockIdx.x == 0) {   // fused ksum partial for this m-tile / L-split
#pragma unroll
        for (int q = 0; q < 8; q++) red[arow0][acol8 + q] = ksp[q];
        __syncthreads();
        if (tid < 128) {
            float s = 0.f;
#pragma unroll
            for (int j = 0; j < 16; j++) s += red[j][tid];
            atomicAdd(&g_ksum[b * TWOM + m0 + tid], s);
        }
    }
}

// ============================================================================
// Kernel 5 (mma): num[b,l,d] = sum_m qp[b,l,m] * kv[b,m,d]
// Tiles 128l x 64d. A direct ldmatrix, B trans (kv's verified mapping).
// Fused: denom (dot with g_ksum during A staging) + epilogue
//   out = num/denom + addproj + b_add   -> g_out
// ============================================================================
__global__ void __launch_bounds__(256, 2) k_num_mma(const float* __restrict__ b_add)
{
    __shared__ __nv_bfloat16 sAhi[128 * TPAD], sAlo[128 * TPAD];  // qp [l][m-chunk]
    __shared__ __nv_bfloat16 sBhi[32 * KTPB],  sBlo[32 * KTPB];   // kv chunk [m][d]
    __shared__ float red2[128][4];

    const int d0 = blockIdx.x * 64;       // 0..3
    const int lt = blockIdx.y * 128;      // 0..15
    const int b  = blockIdx.z;
    const float* qpb = g_qp + (size_t)(b * LSEQ + lt) * TWOM;
    const float* kvb = g_kv + (size_t)b * TWOM * DM + d0;
    const float* ksb = g_ksum + b * TWOM;

    const int tid = threadIdx.x, wid = tid >> 5, lane = tid & 31;
    const int g8 = lane >> 3, r8 = lane & 7;
    const int wm = (wid >> 2) * 64, wn = (wid & 3) * 16;
    const int arow = wm + (lane & 15);
    const int akc  = (lane >> 4) * 8;

    float acc[4][2][4] = {};
    float dn[2] = {0.f, 0.f};

    const int srow0 = tid >> 2, scol8 = (tid & 3) * 8;    // A staging
    const int brow0 = tid >> 3, bcol8 = (tid & 7) * 8;    // B staging (32 rows x 64)

    // prefetch chunk 0
    float pa[2][8], pb[8];
#pragma unroll
    for (int i = 0; i < 2; i++) {
        const float* p = qpb + (size_t)(srow0 + i * 64) * TWOM + scol8;
        *(float4*)&pa[i][0] = *(const float4*)p;
        *(float4*)&pa[i][4] = *(const float4*)(p + 4);
    }
    {
        const float* q = kvb + (size_t)brow0 * DM + bcol8;
        *(float4*)&pb[0] = *(const float4*)q;
        *(float4*)&pb[4] = *(const float4*)(q + 4);
    }

    for (int ch = 0; ch < TWOM / 32; ch++) {
        const int k0 = ch * 32;
#pragma unroll
        for (int i = 0; i < 2; i++) {
            int row = srow0 + i * 64;
            uint32_t hw[4], lw[4];
            cvt8(pa[i], hw, lw);
            const float* ks = ksb + k0 + scol8;
#pragma unroll
            for (int q = 0; q < 8; q++) dn[i] = fmaf(pa[i][q], ks[q], dn[i]);
            *(uint4*)(sAhi + row * TPAD + scol8) = make_uint4(hw[0], hw[1], hw[2], hw[3]);
            *(uint4*)(sAlo + row * TPAD + scol8) = make_uint4(lw[0], lw[1], lw[2], lw[3]);
        }
        {
            uint32_t hw[4], lw[4];
            cvt8(pb, hw, lw);
            int idx = brow0 * KTPB + bcol8;
            *(uint4*)(sBhi + idx) = make_uint4(hw[0], hw[1], hw[2], hw[3]);
            *(uint4*)(sBlo + idx) = make_uint4(lw[0], lw[1], lw[2], lw[3]);
        }
        __syncthreads();

        if (ch + 1 < TWOM / 32) {
            const int k1 = (ch + 1) * 32;
#pragma unroll
            for (int i = 0; i < 2; i++) {
                const float* p = qpb + (size_t)(srow0 + i * 64) * TWOM + k1 + scol8;
                *(float4*)&pa[i][0] = *(const float4*)p;
                *(float4*)&pa[i][4] = *(const float4*)(p + 4);
            }
            const float* q = kvb + (size_t)(k1 + brow0) * DM + bcol8;
            *(float4*)&pb[0] = *(const float4*)q;
            *(float4*)&pb[4] = *(const float4*)(q + 4);
        }

#pragma unroll
        for (int ks2 = 0; ks2 < 2; ks2++) {
            const int kc = ks2 * 16;
            uint32_t ahi[4][4], alo[4][4];
#pragma unroll
            for (int mi = 0; mi < 4; mi++) {
                const int off = (arow + mi * 16) * TPAD + kc + akc;
                ldmx4(ahi[mi], sAhi + off);
                ldmx4(alo[mi], sAlo + off);
            }
            uint32_t bhi[4], blo[4];
            {
                const int off = (kc + r8 + (g8 & 1) * 8) * KTPB + wn + (g8 >> 1) * 8;
                ldmx4t(bhi, sBhi + off);
                ldmx4t(blo, sBlo + off);
            }
#pragma unroll
            for (int mi = 0; mi < 4; mi++)
#pragma unroll
                for (int nj = 0; nj < 2; nj++) {
                    const int o = nj * 2;
                    mma16816(acc[mi][nj], ahi[mi], bhi[o], bhi[o+1]);
                    mma16816(acc[mi][nj], ahi[mi], blo[o], blo[o+1]);
                    mma16816(acc[mi][nj], alo[mi], bhi[o], bhi[o+1]);
                }
        }
        __syncthreads();
    }

    red2[srow0][tid & 3]      = dn[0];
    red2[srow0 + 64][tid & 3] = dn[1];
    __syncthreads();

    const int rr0 = wm + (lane >> 2);
    const int cc0 = d0 + wn + (lane & 3) * 2;
#pragma unroll
    for (int mi = 0; mi < 4; mi++) {
#pragma unroll
        for (int h = 0; h < 2; h++) {
            int rloc = rr0 + mi * 16 + h * 8;
            float den = red2[rloc][0] + red2[rloc][1] + red2[rloc][2] + red2[rloc][3];
            float inv = 1.0f / den;
            int rg = b * LSEQ + lt + rloc;
            const float* addp = g_qkva + (size_t)rg * NPROJ + 3 * DM;
            float* orow = g_out + (size_t)rg * DM;
#pragma unroll
            for (int nj = 0; nj < 2; nj++) {
                int c = cc0 + nj * 8;
                float v0 = acc[mi][nj][h*2]   * inv + addp[c]     + b_add[c];
                float v1 = acc[mi][nj][h*2+1] * inv + addp[c + 1] + b_add[c + 1];
                *(float2*)&orow[c] = make_float2(v0, v1);
            }
        }
    }
}

// ============================================================================
// Kernel 6a: init d_out with b_final.
// ============================================================================
__global__ void k_init_out(float* __restrict__ out, const float* __restrict__ bf)
{
    int i = threadIdx.x;                 // 512 threads
    out[i] = bf[i & 63];
}

// ============================================================================
// Kernel 6b: result[b,c] += sum_f out[b,f] * Wf[c,f]   (split-K, atomics)
// ============================================================================
__global__ void __launch_bounds__(256) k_final(const float* __restrict__ Wf,
                                               float* __restrict__ out)
{
    __shared__ float Ws[64][130];
    __shared__ float Os[8][132];

    const int tid = threadIdx.x;
    const int c  = tid & 63;
    const int bb = tid >> 6;             // 0..3
    float acc0 = 0.f, acc1 = 0.f;
    const int f0 = blockIdx.x * 1024;

    for (int t = 0; t < 1024; t += 128) {
        const int fbase = f0 + t;
#pragma unroll
        for (int i = 0; i < 8; i++) {    // Ws: 2048 float4 / 256 thr
            int v = tid + i * 256;
            int cc = v >> 5, f4 = (v & 31) * 4;
            float4 w = *(const float4*)(Wf + (size_t)cc * FTOT + fbase + f4);
            Ws[cc][f4] = w.x; Ws[cc][f4+1] = w.y; Ws[cc][f4+2] = w.z; Ws[cc][f4+3] = w.w;
        }
        {                                // Os: 256 float4 / 256 thr
            int v = tid;
            int bo = v >> 5, f4 = (v & 31) * 4;
            float4 o = *(const float4*)(g_out + (size_t)bo * FTOT + fbase + f4);
            Os[bo][f4] = o.x; Os[bo][f4+1] = o.y; Os[bo][f4+2] = o.z; Os[bo][f4+3] = o.w;
        }
        __syncthreads();
#pragma unroll 8
        for (int fi = 0; fi < 128; fi++) {
            float w = Ws[c][fi];
            acc0 = fmaf(Os[bb][fi],     w, acc0);
            acc1 = fmaf(Os[bb + 4][fi], w, acc1);
        }
        __syncthreads();
    }
    atomicAdd(&out[bb * NCLASS + c],       acc0);
    atomicAdd(&out[(bb + 4) * NCLASS + c], acc1);
}

// ============================================================================
extern "C" void kernel_launch(void* const* d_in, const int* in_sizes, int n_in,
                              void* d_out, int out_size)
{
    const float* X  = (const float*)d_in[0];
    // d_in[1..6]: unused scalars
    const float* Wq = (const float*)d_in[7];
    const float* Wk = (const float*)d_in[8];
    const float* Wv = (const float*)d_in[9];
    const float* Wa = (const float*)d_in[10];
    const float* bA = (const float*)d_in[11];
    const float* Wf = (const float*)d_in[12];
    const float* bF = (const float*)d_in[13];
    const float* rf = (const float*)d_in[14];
    float* out = (float*)d_out;

    k_zero_acc<<<1024,            256>>>();
    k_proj_mma<<<dim3(16, 128),   256>>>(X, Wq, Wk, Wv, Wa);
    k_rowscale<<<dim3(2048, 2),   256>>>();
    k_phi_mma <<<dim3(4, 128, 2), 256>>>(rf);
    k_kv_mma  <<<dim3(4, 4, 8 * LSPLIT), 256>>>();
    k_num_mma <<<dim3(4, 16, 8),  256>>>(bA);
    k_init_out<<<1, 512>>>(out, bF);
    k_final   <<<512, 256>>>(Wf, out);
}

// round 9
// speedup vs baseline: 1.9422x; 1.0167x over previous
#include <cuda_runtime.h>
#include <cuda_bf16.h>
#include <math.h>
#include <cstdint>

// Problem constants
#define NB     8
#define LSEQ   2048
#define BL     16384          // NB*LSEQ
#define DLEN   512
#define DM     256
#define NPROJ  1024           // Q|K|V|Add concatenated
#define MRF    256
#define TWOM   512
#define NCLASS 64
#define FTOT   (LSEQ*DM)      // 524288 flattened features per batch

#define TWO_PI 6.28318530717958647692f
#define LSPLIT 4              // L-splits for kv kernel

// ---------------- device scratch (allocation-free rule: static globals) ----
__device__ float g_qkva[BL * NPROJ];      // 64 MB : [row,1024]; only V|Add written
__device__ float g_scale_q[BL];
__device__ float g_scale_k[BL];
__device__ float g_qp[BL * TWOM];         // 32 MB
__device__ float g_kp[BL * TWOM];         // 32 MB
__device__ float g_ksum[NB * TWOM];
__device__ float g_kv[NB * TWOM * DM];    // 4 MB
__device__ float g_out[BL * DM];          // 16 MB

// bf16 hi/lo split inputs (written once per launch by k_cvt / k_proj epilogue)
__device__ __nv_bfloat16 g_x_hi[BL * DLEN],  g_x_lo[BL * DLEN];     // 16+16 MB
__device__ __nv_bfloat16 g_w_hi[1024 * DLEN], g_w_lo[1024 * DLEN];  // 1+1 MB (Q|K|V|Add rows)
__device__ __nv_bfloat16 g_rf_hi[MRF * MRF],  g_rf_lo[MRF * MRF];
__device__ __nv_bfloat16 g_qk_hi[BL * 512],  g_qk_lo[BL * 512];     // [row][Q 0..255 | K 256..511]

// ============================================================================
// helpers
// ============================================================================
__device__ __forceinline__ uint32_t smem_u32(const void* p) {
    uint32_t a;
    asm("{ .reg .u64 t; cvta.to.shared.u64 t, %1; cvt.u32.u64 %0, t; }" : "=r"(a) : "l"(p));
    return a;
}
__device__ __forceinline__ void ldmx4(uint32_t r[4], const void* p) {
    uint32_t a = smem_u32(p);
    asm volatile("ldmatrix.sync.aligned.m8n8.x4.shared.b16 {%0,%1,%2,%3}, [%4];"
                 : "=r"(r[0]), "=r"(r[1]), "=r"(r[2]), "=r"(r[3]) : "r"(a));
}
__device__ __forceinline__ void ldmx4t(uint32_t r[4], const void* p) {
    uint32_t a = smem_u32(p);
    asm volatile("ldmatrix.sync.aligned.m8n8.x4.trans.shared.b16 {%0,%1,%2,%3}, [%4];"
                 : "=r"(r[0]), "=r"(r[1]), "=r"(r[2]), "=r"(r[3]) : "r"(a));
}
__device__ __forceinline__ void mma16816(float d[4], const uint32_t a[4],
                                         uint32_t b0, uint32_t b1) {
    asm volatile(
        "mma.sync.aligned.m16n8k16.row.col.f32.bf16.bf16.f32 "
        "{%0,%1,%2,%3}, {%4,%5,%6,%7}, {%8,%9}, {%0,%1,%2,%3};"
        : "+f"(d[0]), "+f"(d[1]), "+f"(d[2]), "+f"(d[3])
        : "r"(a[0]), "r"(a[1]), "r"(a[2]), "r"(a[3]), "r"(b0), "r"(b1));
}
#define CP16(dst, src) asm volatile("cp.async.cg.shared.global [%0], [%1], 16;" :: "r"(dst), "l"(src))
#define CP_COMMIT()    asm volatile("cp.async.commit_group;" ::: "memory")
#define CP_WAIT1()     asm volatile("cp.async.wait_group 1;" ::: "memory")
#define CP_WAIT0()     asm volatile("cp.async.wait_group 0;" ::: "memory")

#define TPAD 40    // [row][32 k] padded stride (80B rows: 16B aligned, conflict-free)
#define KTP  136
#define KTPB 72

__device__ __forceinline__ void cvt8(const float xs[8], uint32_t hw[4], uint32_t lw[4]) {
#pragma unroll
    for (int q = 0; q < 4; q++) {
        __nv_bfloat16 h0 = __float2bfloat16_rn(xs[2*q]);
        __nv_bfloat16 h1 = __float2bfloat16_rn(xs[2*q+1]);
        hw[q] = (uint32_t)__bfloat16_as_ushort(h0) | ((uint32_t)__bfloat16_as_ushort(h1) << 16);
        __nv_bfloat16 l0 = __float2bfloat16_rn(xs[2*q]   - __bfloat162float(h0));
        __nv_bfloat16 l1 = __float2bfloat16_rn(xs[2*q+1] - __bfloat162float(h1));
        lw[q] = (uint32_t)__bfloat16_as_ushort(l0) | ((uint32_t)__bfloat16_as_ushort(l1) << 16);
    }
}
__device__ __forceinline__ void stage8_cvt(const float* __restrict__ p,
                                           __nv_bfloat16* __restrict__ hi,
                                           __nv_bfloat16* __restrict__ lo,
                                           int idx) {
    float4 u = *(const float4*)p;
    float4 v = *(const float4*)(p + 4);
    float xs[8] = {u.x, u.y, u.z, u.w, v.x, v.y, v.z, v.w};
    uint32_t hw[4], lw[4];
    cvt8(xs, hw, lw);
    *(uint4*)(hi + idx) = make_uint4(hw[0], hw[1], hw[2], hw[3]);
    *(uint4*)(lo + idx) = make_uint4(lw[0], lw[1], lw[2], lw[3]);
}

// ============================================================================
// cp.async ping-pong GEMM core: C[128,64] = A[128,K] @ B[64,K]^T, bf16x3.
// Warp grid 4x2 (warp tile 32m x 32n). acc[mi 2][nj 4][4].
// smem stage (bf16 elems): AHI 0, ALO 5120, BHI 10240, BLO 12800; stage 15360.
// ============================================================================
#define ST_AHI 0
#define ST_ALO 5120
#define ST_BHI 10240
#define ST_BLO 12800
#define ST_SZ  15360
#define SMEM_DYN (2 * ST_SZ * 2)    // 61440 bytes

template<int KCH>
__device__ __forceinline__ void gemm_core_cp(
    const __nv_bfloat16* __restrict__ Ahi, const __nv_bfloat16* __restrict__ Alo, int astr,
    const __nv_bfloat16* __restrict__ Bhi, const __nv_bfloat16* __restrict__ Blo, int bstr,
    float acc[2][4][4], __nv_bfloat16* sm)
{
    const int tid = threadIdx.x, wid = tid >> 5, lane = tid & 31;
    const int wm = (wid >> 1) * 32, wn = (wid & 1) * 32;
    const int arow = wm + (lane & 15), akc = (lane >> 4) * 8;
    const int brow = wn + (lane >> 4) * 8 + (lane & 7), bkc = ((lane >> 3) & 1) * 8;

    const int rA = tid >> 1, cA = (tid & 1) * 2;   // A: 128 rows x 4 16B-chunks
    const int rB = tid >> 2, cB = tid & 3;         // B: 64 rows x 4 16B-chunks

    auto issue = [&](int st, int k0) {
        __nv_bfloat16* base = sm + st * ST_SZ;
#pragma unroll
        for (int j = 0; j < 2; j++) {
            int c = cA + j;
            CP16(smem_u32(base + ST_AHI + rA * TPAD + c * 8), Ahi + (size_t)rA * astr + k0 + c * 8);
            CP16(smem_u32(base + ST_ALO + rA * TPAD + c * 8), Alo + (size_t)rA * astr + k0 + c * 8);
        }
        CP16(smem_u32(base + ST_BHI + rB * TPAD + cB * 8), Bhi + (size_t)rB * bstr + k0 + cB * 8);
        CP16(smem_u32(base + ST_BLO + rB * TPAD + cB * 8), Blo + (size_t)rB * bstr + k0 + cB * 8);
        CP_COMMIT();
    };

    issue(0, 0);
    for (int ch = 0; ch < KCH; ch++) {
        if (ch + 1 < KCH) { issue((ch + 1) & 1, (ch + 1) * 32); CP_WAIT1(); }
        else              { CP_WAIT0(); }
        __syncthreads();

        const __nv_bfloat16* base = sm + (ch & 1) * ST_SZ;
#pragma unroll
        for (int ks = 0; ks < 2; ks++) {
            const int kc = ks * 16;
            uint32_t ahi[2][4], alo[2][4];
#pragma unroll
            for (int mi = 0; mi < 2; mi++) {
                const int off = (arow + mi * 16) * TPAD + kc + akc;
                ldmx4(ahi[mi], base + ST_AHI + off);
                ldmx4(alo[mi], base + ST_ALO + off);
            }
            uint32_t bh[2][4], bl[2][4];
#pragma unroll
            for (int np = 0; np < 2; np++) {
                const int off = (brow + np * 16) * TPAD + kc + bkc;
                ldmx4(bh[np], base + ST_BHI + off);
                ldmx4(bl[np], base + ST_BLO + off);
            }
#pragma unroll
            for (int mi = 0; mi < 2; mi++)
#pragma unroll
                for (int nj = 0; nj < 4; nj++) {
                    const int np = nj >> 1, o = (nj & 1) * 2;
                    mma16816(acc[mi][nj], ahi[mi], bh[np][o], bh[np][o+1]);
                    mma16816(acc[mi][nj], ahi[mi], bl[np][o], bl[np][o+1]);
                    mma16816(acc[mi][nj], alo[mi], bh[np][o], bh[np][o+1]);
                }
        }
        __syncthreads();
    }
}

// ============================================================================
// Kernel -1: convert inputs to bf16 hi/lo (X, Wcat, rf)
// ============================================================================
#define NXE (BL * DLEN)        // 8388608
#define NWE (1024 * DLEN)      // 524288
#define NRE (MRF * MRF)        // 65536
#define CVT_BLOCKS ((NXE + NWE + NRE) / 8 / 256)   // 4384 exactly

__global__ void k_cvt(const float* __restrict__ X,
                      const float* __restrict__ Wq, const float* __restrict__ Wk,
                      const float* __restrict__ Wv, const float* __restrict__ Wa,
                      const float* __restrict__ rf)
{
    size_t base = ((size_t)blockIdx.x * 256 + threadIdx.x) * 8;
    const float* src;
    __nv_bfloat16 *dhi, *dlo;
    if (base < NXE) {
        src = X + base; dhi = g_x_hi + base; dlo = g_x_lo + base;
    } else if (base < NXE + NWE) {
        size_t off = base - NXE;
        int sel = (int)(off >> 17);                  // 131072 elems per W
        const float* W = (sel == 0) ? Wq : (sel == 1) ? Wk : (sel == 2) ? Wv : Wa;
        src = W + (off & 131071); dhi = g_w_hi + off; dlo = g_w_lo + off;
    } else {
        size_t off = base - NXE - NWE;
        src = rf + off; dhi = g_rf_hi + off; dlo = g_rf_lo + off;
    }
    float4 u = *(const float4*)src, v = *(const float4*)(src + 4);
    float xs[8] = {u.x, u.y, u.z, u.w, v.x, v.y, v.z, v.w};
    uint32_t hw[4], lw[4];
    cvt8(xs, hw, lw);
    *(uint4*)dhi = make_uint4(hw[0], hw[1], hw[2], hw[3]);
    *(uint4*)dlo = make_uint4(lw[0], lw[1], lw[2], lw[3]);
}

// ============================================================================
// Kernel 0: zero kv + ksum accumulators
// ============================================================================
__global__ void k_zero_acc()
{
    int idx = blockIdx.x * 256 + threadIdx.x;     // 1024 blocks
    ((float4*)g_kv)[idx] = make_float4(0.f, 0.f, 0.f, 0.f);
    if (idx < NB * TWOM / 4)
        ((float4*)g_ksum)[idx] = make_float4(0.f, 0.f, 0.f, 0.f);
}

// ============================================================================
// Kernel 1: proj. bn 0..7 -> Q|K bf16 hi/lo; bn 8..15 -> V|Add fp32 qkva.
// ============================================================================
__global__ void __launch_bounds__(256, 2) k_proj_mma()
{
    extern __shared__ __nv_bfloat16 sm[];
    const int bn = blockIdx.x;            // 0..15
    const int bm = blockIdx.y;            // 0..127

    const __nv_bfloat16* Ah = g_x_hi + (size_t)bm * 128 * DLEN;
    const __nv_bfloat16* Al = g_x_lo + (size_t)bm * 128 * DLEN;
    const __nv_bfloat16* Bh = g_w_hi + (size_t)bn * 64 * DLEN;
    const __nv_bfloat16* Bl = g_w_lo + (size_t)bn * 64 * DLEN;

    float acc[2][4][4] = {};
    gemm_core_cp<16>(Ah, Al, DLEN, Bh, Bl, DLEN, acc, sm);

    const int tid = threadIdx.x, wid = tid >> 5, lane = tid & 31;
    const int r0 = bm * 128 + (wid >> 1) * 32 + (lane >> 2);
    const int c0 = bn * 64 + (wid & 1) * 32 + (lane & 3) * 2;   // global col

    if (bn < 8) {   // Q|K -> bf16 hi/lo, col 0..511
#pragma unroll
        for (int mi = 0; mi < 2; mi++)
#pragma unroll
            for (int nj = 0; nj < 4; nj++) {
#pragma unroll
                for (int h = 0; h < 2; h++) {
                    int r = r0 + mi * 16 + h * 8, c = c0 + nj * 8;
                    float v0 = acc[mi][nj][h*2], v1 = acc[mi][nj][h*2+1];
                    __nv_bfloat16 h0 = __float2bfloat16_rn(v0);
                    __nv_bfloat16 h1 = __float2bfloat16_rn(v1);
                    __nv_bfloat16 l0 = __float2bfloat16_rn(v0 - __bfloat162float(h0));
                    __nv_bfloat16 l1 = __float2bfloat16_rn(v1 - __bfloat162float(h1));
                    size_t idx = (size_t)r * 512 + c;
                    *(uint32_t*)(g_qk_hi + idx) =
                        (uint32_t)__bfloat16_as_ushort(h0) | ((uint32_t)__bfloat16_as_ushort(h1) << 16);
                    *(uint32_t*)(g_qk_lo + idx) =
                        (uint32_t)__bfloat16_as_ushort(l0) | ((uint32_t)__bfloat16_as_ushort(l1) << 16);
                }
            }
    } else {        // V|Add -> fp32 qkva, col 512..1023
#pragma unroll
        for (int mi = 0; mi < 2; mi++)
#pragma unroll
            for (int nj = 0; nj < 4; nj++) {
                int r = r0 + mi * 16, c = c0 + nj * 8;
                *(float2*)&g_qkva[(size_t)r * NPROJ + c]       = make_float2(acc[mi][nj][0], acc[mi][nj][1]);
                *(float2*)&g_qkva[(size_t)(r + 8) * NPROJ + c] = make_float2(acc[mi][nj][2], acc[mi][nj][3]);
            }
    }
}

// ============================================================================
// Kernel 2: rowscale from bf16 hi/lo Q|K
// ============================================================================
__global__ void k_rowscale()
{
    int warp = (blockIdx.x * blockDim.x + threadIdx.x) >> 5;
    int lane = threadIdx.x & 31;
    int isK = blockIdx.y;
    if (warp >= BL) return;
    const __nv_bfloat16* hi = g_qk_hi + (size_t)warp * 512 + (isK ? DM : 0);
    const __nv_bfloat16* lo = g_qk_lo + (size_t)warp * 512 + (isK ? DM : 0);
    float s = 0.f;
#pragma unroll
    for (int i = lane; i < DM; i += 32) {
        float v = __bfloat162float(hi[i]) + __bfloat162float(lo[i]);
        s = fmaf(v, v, s);
    }
#pragma unroll
    for (int o = 16; o; o >>= 1) s += __shfl_xor_sync(0xFFFFFFFFu, s, o);
    if (lane == 0) {
        float sc = expf(0.5f * s) * 0.0625f;
        (isK ? g_scale_k : g_scale_q)[warp] = sc;
    }
}

// ============================================================================
// Kernel 3: phi.  (Q or K)[128,256] @ rf[64-tile,256]^T; sincos epilogue.
// ============================================================================
__global__ void __launch_bounds__(256, 2) k_phi_mma()
{
    extern __shared__ __nv_bfloat16 sm[];
    const int bn = blockIdx.x;            // 0..3
    const int bm = blockIdx.y;            // 0..127
    const int isK = blockIdx.z;

    const __nv_bfloat16* Ah = g_qk_hi + (size_t)bm * 128 * 512 + (isK ? DM : 0);
    const __nv_bfloat16* Al = g_qk_lo + (size_t)bm * 128 * 512 + (isK ? DM : 0);
    const __nv_bfloat16* Bh = g_rf_hi + (size_t)bn * 64 * MRF;
    const __nv_bfloat16* Bl = g_rf_lo + (size_t)bn * 64 * MRF;

    float acc[2][4][4] = {};
    gemm_core_cp<8>(Ah, Al, 512, Bh, Bl, MRF, acc, sm);

    float* OUT = isK ? g_kp : g_qp;
    const float* SC = isK ? g_scale_k : g_scale_q;

    const int tid = threadIdx.x, wid = tid >> 5, lane = tid & 31;
    const int r0 = bm * 128 + (wid >> 1) * 32 + (lane >> 2);
    const int c0 = bn * 64 + (wid & 1) * 32 + (lane & 3) * 2;   // feature 0..255
#pragma unroll
    for (int mi = 0; mi < 2; mi++) {
        int r = r0 + mi * 16;
        float sa = SC[r], sb = SC[r + 8];
        float* rowa = OUT + (size_t)r * TWOM;
        float* rowb = OUT + (size_t)(r + 8) * TWOM;
#pragma unroll
        for (int nj = 0; nj < 4; nj++) {
            int c = c0 + nj * 8;
            float s0, cz0, s1, cz1, s2, cz2, s3, cz3;
            sincosf(TWO_PI * acc[mi][nj][0], &s0, &cz0);
            sincosf(TWO_PI * acc[mi][nj][1], &s1, &cz1);
            sincosf(TWO_PI * acc[mi][nj][2], &s2, &cz2);
            sincosf(TWO_PI * acc[mi][nj][3], &s3, &cz3);
            *(float2*)&rowa[c]      = make_float2(s0 * sa,  s1 * sa);
            *(float2*)&rowa[c + DM] = make_float2(cz0 * sa, cz1 * sa);
            *(float2*)&rowb[c]      = make_float2(s2 * sb,  s3 * sb);
            *(float2*)&rowb[c + DM] = make_float2(cz2 * sb, cz3 * sb);
        }
    }
}

// ============================================================================
// Kernel 4 (mma): kv[b, m, d] += sum_{l in split} kp[b,l,m] * v[b,l,d]
// (unchanged from round 8)
// ============================================================================
__global__ void __launch_bounds__(256, 2) k_kv_mma()
{
    __shared__ __nv_bfloat16 sAhi[32 * KTP],  sAlo[32 * KTP];
    __shared__ __nv_bfloat16 sBhi[32 * KTPB], sBlo[32 * KTPB];
    __shared__ float red[16][128];

    const int d0 = blockIdx.x * 64;
    const int m0 = blockIdx.y * 128;
    const int b  = blockIdx.z >> 2;
    const int sp = blockIdx.z & 3;
    const float* kpb = g_kp   + (size_t)b * LSEQ * TWOM  + m0;
    const float* vb  = g_qkva + (size_t)b * LSEQ * NPROJ + 2 * DM + d0;

    const int tid = threadIdx.x, wid = tid >> 5, lane = tid & 31;
    const int g8 = lane >> 3, r8 = lane & 7;
    const int wm = (wid >> 2) * 64, wn = (wid & 3) * 16;

    float acc[4][2][4] = {};
    float ksp[8] = {};

    const int arow0 = tid >> 4, acol8 = (tid & 15) * 8;
    const int brow0 = tid >> 3, bcol8 = (tid & 7) * 8;

    const int ch0 = sp * (LSEQ / 32 / LSPLIT);
    const int ch1 = ch0 + (LSEQ / 32 / LSPLIT);
    for (int ch = ch0; ch < ch1; ch++) {
        const int l0 = ch * 32;
#pragma unroll
        for (int i = 0; i < 2; i++) {
            int row = arow0 + i * 16;
            const float* p = kpb + (size_t)(l0 + row) * TWOM + acol8;
            float4 u = *(const float4*)p, v4 = *(const float4*)(p + 4);
            float xs[8] = {u.x, u.y, u.z, u.w, v4.x, v4.y, v4.z, v4.w};
            uint32_t hw[4], lw[4];
            cvt8(xs, hw, lw);
#pragma unroll
            for (int q = 0; q < 8; q++) ksp[q] += xs[q];
            *(uint4*)(sAhi + row * KTP + acol8) = make_uint4(hw[0], hw[1], hw[2], hw[3]);
            *(uint4*)(sAlo + row * KTP + acol8) = make_uint4(lw[0], lw[1], lw[2], lw[3]);
        }
        stage8_cvt(vb + (size_t)(l0 + brow0) * NPROJ + bcol8, sBhi, sBlo, brow0 * KTPB + bcol8);
        __syncthreads();

#pragma unroll
        for (int ks = 0; ks < 2; ks++) {
            const int kc = ks * 16;
            uint32_t ahi[4][4], alo[4][4];
#pragma unroll
            for (int mi = 0; mi < 4; mi++) {
                const int off = (kc + r8 + (g8 >> 1) * 8) * KTP + wm + mi * 16 + (g8 & 1) * 8;
                ldmx4t(ahi[mi], sAhi + off);
                ldmx4t(alo[mi], sAlo + off);
            }
            uint32_t bhi[4], blo[4];
            {
                const int off = (kc + r8 + (g8 & 1) * 8) * KTPB + wn + (g8 >> 1) * 8;
                ldmx4t(bhi, sBhi + off);
                ldmx4t(blo, sBlo + off);
            }
#pragma unroll
            for (int mi = 0; mi < 4; mi++)
#pragma unroll
                for (int nj = 0; nj < 2; nj++) {
                    const int o = nj * 2;
                    mma16816(acc[mi][nj], ahi[mi], bhi[o], bhi[o+1]);
                    mma16816(acc[mi][nj], ahi[mi], blo[o], blo[o+1]);
                    mma16816(acc[mi][nj], alo[mi], bhi[o], bhi[o+1]);
                }
        }
        __syncthreads();
    }

    const int rr0 = m0 + wm + (lane >> 2);
    const int cc0 = d0 + wn + (lane & 3) * 2;
#pragma unroll
    for (int mi = 0; mi < 4; mi++)
#pragma unroll
        for (int nj = 0; nj < 2; nj++) {
            int r = rr0 + mi * 16, c = cc0 + nj * 8;
            float* p0 = &g_kv[((size_t)b * TWOM + r) * DM + c];
            float* p1 = &g_kv[((size_t)b * TWOM + r + 8) * DM + c];
            atomicAdd(p0,     acc[mi][nj][0]);
            atomicAdd(p0 + 1, acc[mi][nj][1]);
            atomicAdd(p1,     acc[mi][nj][2]);
            atomicAdd(p1 + 1, acc[mi][nj][3]);
        }

    if (blockIdx.x == 0) {
#pragma unroll
        for (int q = 0; q < 8; q++) red[arow0][acol8 + q] = ksp[q];
        __syncthreads();
        if (tid < 128) {
            float s = 0.f;
#pragma unroll
            for (int j = 0; j < 16; j++) s += red[j][tid];
            atomicAdd(&g_ksum[b * TWOM + m0 + tid], s);
        }
    }
}

// ============================================================================
// Kernel 5 (mma): num + fused denom + epilogue   (unchanged from round 8)
// ============================================================================
__global__ void __launch_bounds__(256, 2) k_num_mma(const float* __restrict__ b_add)
{
    __shared__ __nv_bfloat16 sAhi[128 * TPAD], sAlo[128 * TPAD];
    __shared__ __nv_bfloat16 sBhi[32 * KTPB],  sBlo[32 * KTPB];
    __shared__ float red2[128][4];

    const int d0 = blockIdx.x * 64;
    const int lt = blockIdx.y * 128;
    const int b  = blockIdx.z;
    const float* qpb = g_qp + (size_t)(b * LSEQ + lt) * TWOM;
    const float* kvb = g_kv + (size_t)b * TWOM * DM + d0;
    const float* ksb = g_ksum + b * TWOM;

    const int tid = threadIdx.x, wid = tid >> 5, lane = tid & 31;
    const int g8 = lane >> 3, r8 = lane & 7;
    const int wm = (wid >> 2) * 64, wn = (wid & 3) * 16;
    const int arow = wm + (lane & 15);
    const int akc  = (lane >> 4) * 8;

    float acc[4][2][4] = {};
    float dn[2] = {0.f, 0.f};

    const int srow0 = tid >> 2, scol8 = (tid & 3) * 8;
    const int brow0 = tid >> 3, bcol8 = (tid & 7) * 8;

    float pa[2][8], pb[8];
#pragma unroll
    for (int i = 0; i < 2; i++) {
        const float* p = qpb + (size_t)(srow0 + i * 64) * TWOM + scol8;
        *(float4*)&pa[i][0] = *(const float4*)p;
        *(float4*)&pa[i][4] = *(const float4*)(p + 4);
    }
    {
        const float* q = kvb + (size_t)brow0 * DM + bcol8;
        *(float4*)&pb[0] = *(const float4*)q;
        *(float4*)&pb[4] = *(const float4*)(q + 4);
    }

    for (int ch = 0; ch < TWOM / 32; ch++) {
        const int k0 = ch * 32;
#pragma unroll
        for (int i = 0; i < 2; i++) {
            int row = srow0 + i * 64;
            uint32_t hw[4], lw[4];
            cvt8(pa[i], hw, lw);
            const float* ks = ksb + k0 + scol8;
#pragma unroll
            for (int q = 0; q < 8; q++) dn[i] = fmaf(pa[i][q], ks[q], dn[i]);
            *(uint4*)(sAhi + row * TPAD + scol8) = make_uint4(hw[0], hw[1], hw[2], hw[3]);
            *(uint4*)(sAlo + row * TPAD + scol8) = make_uint4(lw[0], lw[1], lw[2], lw[3]);
        }
        {
            uint32_t hw[4], lw[4];
            cvt8(pb, hw, lw);
            int idx = brow0 * KTPB + bcol8;
            *(uint4*)(sBhi + idx) = make_uint4(hw[0], hw[1], hw[2], hw[3]);
            *(uint4*)(sBlo + idx) = make_uint4(lw[0], lw[1], lw[2], lw[3]);
        }
        __syncthreads();

        if (ch + 1 < TWOM / 32) {
            const int k1 = (ch + 1) * 32;
#pragma unroll
            for (int i = 0; i < 2; i++) {
                const float* p = qpb + (size_t)(srow0 + i * 64) * TWOM + k1 + scol8;
                *(float4*)&pa[i][0] = *(const float4*)p;
                *(float4*)&pa[i][4] = *(const float4*)(p + 4);
            }
            const float* q = kvb + (size_t)(k1 + brow0) * DM + bcol8;
            *(float4*)&pb[0] = *(const float4*)q;
            *(float4*)&pb[4] = *(const float4*)(q + 4);
        }

#pragma unroll
        for (int ks2 = 0; ks2 < 2; ks2++) {
            const int kc = ks2 * 16;
            uint32_t ahi[4][4], alo[4][4];
#pragma unroll
            for (int mi = 0; mi < 4; mi++) {
                const int off = (arow + mi * 16) * TPAD + kc + akc;
                ldmx4(ahi[mi], sAhi + off);
                ldmx4(alo[mi], sAlo + off);
            }
            uint32_t bhi[4], blo[4];
            {
                const int off = (kc + r8 + (g8 & 1) * 8) * KTPB + wn + (g8 >> 1) * 8;
                ldmx4t(bhi, sBhi + off);
                ldmx4t(blo, sBlo + off);
            }
#pragma unroll
            for (int mi = 0; mi < 4; mi++)
#pragma unroll
                for (int nj = 0; nj < 2; nj++) {
                    const int o = nj * 2;
                    mma16816(acc[mi][nj], ahi[mi], bhi[o], bhi[o+1]);
                    mma16816(acc[mi][nj], ahi[mi], blo[o], blo[o+1]);
                    mma16816(acc[mi][nj], alo[mi], bhi[o], bhi[o+1]);
                }
        }
        __syncthreads();
    }

    red2[srow0][tid & 3]      = dn[0];
    red2[srow0 + 64][tid & 3] = dn[1];
    __syncthreads();

    const int rr0 = wm + (lane >> 2);
    const int cc0 = d0 + wn + (lane & 3) * 2;
#pragma unroll
    for (int mi = 0; mi < 4; mi++) {
#pragma unroll
        for (int h = 0; h < 2; h++) {
            int rloc = rr0 + mi * 16 + h * 8;
            float den = red2[rloc][0] + red2[rloc][1] + red2[rloc][2] + red2[rloc][3];
            float inv = 1.0f / den;
            int rg = b * LSEQ + lt + rloc;
            const float* addp = g_qkva + (size_t)rg * NPROJ + 3 * DM;
            float* orow = g_out + (size_t)rg * DM;
#pragma unroll
            for (int nj = 0; nj < 2; nj++) {
                int c = cc0 + nj * 8;
                float v0 = acc[mi][nj][h*2]   * inv + addp[c]     + b_add[c];
                float v1 = acc[mi][nj][h*2+1] * inv + addp[c + 1] + b_add[c + 1];
                *(float2*)&orow[c] = make_float2(v0, v1);
            }
        }
    }
}

// ============================================================================
// Kernel 6a: init d_out with b_final.
// ============================================================================
__global__ void k_init_out(float* __restrict__ out, const float* __restrict__ bf)
{
    int i = threadIdx.x;
    out[i] = bf[i & 63];
}

// ============================================================================
// Kernel 6b: final GEMM (split-K atomics)
// ============================================================================
__global__ void __launch_bounds__(256) k_final(const float* __restrict__ Wf,
                                               float* __restrict__ out)
{
    __shared__ float Ws[64][130];
    __shared__ float Os[8][132];

    const int tid = threadIdx.x;
    const int c  = tid & 63;
    const int bb = tid >> 6;
    float acc0 = 0.f, acc1 = 0.f;
    const int f0 = blockIdx.x * 1024;

    for (int t = 0; t < 1024; t += 128) {
        const int fbase = f0 + t;
#pragma unroll
        for (int i = 0; i < 8; i++) {
            int v = tid + i * 256;
            int cc = v >> 5, f4 = (v & 31) * 4;
            float4 w = *(const float4*)(Wf + (size_t)cc * FTOT + fbase + f4);
            Ws[cc][f4] = w.x; Ws[cc][f4+1] = w.y; Ws[cc][f4+2] = w.z; Ws[cc][f4+3] = w.w;
        }
        {
            int v = tid;
            int bo = v >> 5, f4 = (v & 31) * 4;
            float4 o = *(const float4*)(g_out + (size_t)bo * FTOT + fbase + f4);
            Os[bo][f4] = o.x; Os[bo][f4+1] = o.y; Os[bo][f4+2] = o.z; Os[bo][f4+3] = o.w;
        }
        __syncthreads();
#pragma unroll 8
        for (int fi = 0; fi < 128; fi++) {
            float w = Ws[c][fi];
            acc0 = fmaf(Os[bb][fi],     w, acc0);
            acc1 = fmaf(Os[bb + 4][fi], w, acc1);
        }
        __syncthreads();
    }
    atomicAdd(&out[bb * NCLASS + c],       acc0);
    atomicAdd(&out[(bb + 4) * NCLASS + c], acc1);
}

// ============================================================================
extern "C" void kernel_launch(void* const* d_in, const int* in_sizes, int n_in,
                              void* d_out, int out_size)
{
    const float* X  = (const float*)d_in[0];
    // d_in[1..6]: unused scalars
    const float* Wq = (const float*)d_in[7];
    const float* Wk = (const float*)d_in[8];
    const float* Wv = (const float*)d_in[9];
    const float* Wa = (const float*)d_in[10];
    const float* bA = (const float*)d_in[11];
    const float* Wf = (const float*)d_in[12];
    const float* bF = (const float*)d_in[13];
    const float* rf = (const float*)d_in[14];
    float* out = (float*)d_out;

    static bool attr_done = false;
    if (!attr_done) {
        cudaFuncSetAttribute(k_proj_mma, cudaFuncAttributeMaxDynamicSharedMemorySize, SMEM_DYN);
        cudaFuncSetAttribute(k_phi_mma,  cudaFuncAttributeMaxDynamicSharedMemorySize, SMEM_DYN);
        attr_done = true;
    }

    k_zero_acc<<<1024,            256>>>();
    k_cvt     <<<CVT_BLOCKS,      256>>>(X, Wq, Wk, Wv, Wa, rf);
    k_proj_mma<<<dim3(16, 128),   256, SMEM_DYN>>>();
    k_rowscale<<<dim3(2048, 2),   256>>>();
    k_phi_mma <<<dim3(4, 128, 2), 256, SMEM_DYN>>>();
    k_kv_mma  <<<dim3(4, 4, 8 * LSPLIT), 256>>>();
    k_num_mma <<<dim3(4, 16, 8),  256>>>(bA);
    k_init_out<<<1, 512>>>(out, bF);
    k_final   <<<512, 256>>>(Wf, out);
}

// round 10
// speedup vs baseline: 1.9999x; 1.0297x over previous
#include <cuda_runtime.h>
#include <cuda_bf16.h>
#include <math.h>
#include <cstdint>

// Problem constants
#define NB     8
#define LSEQ   2048
#define BL     16384          // NB*LSEQ
#define DLEN   512
#define DM     256
#define NPROJ  1024           // Q|K|V|Add concatenated
#define MRF    256
#define TWOM   512
#define NCLASS 64
#define FTOT   (LSEQ*DM)      // 524288 flattened features per batch

#define TWO_PI 6.28318530717958647692f
#define LSPLIT 4              // L-splits for kv kernel

// ---------------- device scratch (allocation-free rule: static globals) ----
__device__ float g_qkva[BL * NPROJ];      // 64 MB : [row,1024]; only V|Add written
__device__ float g_scale_q[BL];
__device__ float g_scale_k[BL];
__device__ float g_qp[BL * TWOM];         // 32 MB
__device__ float g_kp[BL * TWOM];         // 32 MB
__device__ float g_ksum[NB * TWOM];
__device__ float g_kv[NB * TWOM * DM];    // 4 MB
__device__ float g_out[BL * DM];          // 16 MB

// bf16 hi/lo split inputs (written once per launch by k_cvt / k_proj epilogue)
__device__ __nv_bfloat16 g_x_hi[BL * DLEN],  g_x_lo[BL * DLEN];     // 16+16 MB
__device__ __nv_bfloat16 g_w_hi[1024 * DLEN], g_w_lo[1024 * DLEN];  // 1+1 MB
__device__ __nv_bfloat16 g_rf_hi[MRF * MRF],  g_rf_lo[MRF * MRF];
__device__ __nv_bfloat16 g_qk_hi[BL * 512],  g_qk_lo[BL * 512];     // [row][Q 0..255 | K 256..511]

// ============================================================================
// helpers
// ============================================================================
__device__ __forceinline__ uint32_t smem_u32(const void* p) {
    uint32_t a;
    asm("{ .reg .u64 t; cvta.to.shared.u64 t, %1; cvt.u32.u64 %0, t; }" : "=r"(a) : "l"(p));
    return a;
}
__device__ __forceinline__ void ldmx4(uint32_t r[4], const void* p) {
    uint32_t a = smem_u32(p);
    asm volatile("ldmatrix.sync.aligned.m8n8.x4.shared.b16 {%0,%1,%2,%3}, [%4];"
                 : "=r"(r[0]), "=r"(r[1]), "=r"(r[2]), "=r"(r[3]) : "r"(a));
}
__device__ __forceinline__ void ldmx4t(uint32_t r[4], const void* p) {
    uint32_t a = smem_u32(p);
    asm volatile("ldmatrix.sync.aligned.m8n8.x4.trans.shared.b16 {%0,%1,%2,%3}, [%4];"
                 : "=r"(r[0]), "=r"(r[1]), "=r"(r[2]), "=r"(r[3]) : "r"(a));
}
__device__ __forceinline__ void mma16816(float d[4], const uint32_t a[4],
                                         uint32_t b0, uint32_t b1) {
    asm volatile(
        "mma.sync.aligned.m16n8k16.row.col.f32.bf16.bf16.f32 "
        "{%0,%1,%2,%3}, {%4,%5,%6,%7}, {%8,%9}, {%0,%1,%2,%3};"
        : "+f"(d[0]), "+f"(d[1]), "+f"(d[2]), "+f"(d[3])
        : "r"(a[0]), "r"(a[1]), "r"(a[2]), "r"(a[3]), "r"(b0), "r"(b1));
}
#define CP16(dst, src) asm volatile("cp.async.cg.shared.global [%0], [%1], 16;" :: "r"(dst), "l"(src))
#define CP_COMMIT()    asm volatile("cp.async.commit_group;" ::: "memory")
#define CP_WAIT1()     asm volatile("cp.async.wait_group 1;" ::: "memory")
#define CP_WAIT0()     asm volatile("cp.async.wait_group 0;" ::: "memory")

#define TPAD 40    // [row][32 k] padded stride (80B rows: 16B aligned, conflict-free)
#define KTP  136
#define KTPB 72

__device__ __forceinline__ void cvt8(const float xs[8], uint32_t hw[4], uint32_t lw[4]) {
#pragma unroll
    for (int q = 0; q < 4; q++) {
        __nv_bfloat16 h0 = __float2bfloat16_rn(xs[2*q]);
        __nv_bfloat16 h1 = __float2bfloat16_rn(xs[2*q+1]);
        hw[q] = (uint32_t)__bfloat16_as_ushort(h0) | ((uint32_t)__bfloat16_as_ushort(h1) << 16);
        __nv_bfloat16 l0 = __float2bfloat16_rn(xs[2*q]   - __bfloat162float(h0));
        __nv_bfloat16 l1 = __float2bfloat16_rn(xs[2*q+1] - __bfloat162float(h1));
        lw[q] = (uint32_t)__bfloat16_as_ushort(l0) | ((uint32_t)__bfloat16_as_ushort(l1) << 16);
    }
}
__device__ __forceinline__ void stage8_cvt(const float* __restrict__ p,
                                           __nv_bfloat16* __restrict__ hi,
                                           __nv_bfloat16* __restrict__ lo,
                                           int idx) {
    float4 u = *(const float4*)p;
    float4 v = *(const float4*)(p + 4);
    float xs[8] = {u.x, u.y, u.z, u.w, v.x, v.y, v.z, v.w};
    uint32_t hw[4], lw[4];
    cvt8(xs, hw, lw);
    *(uint4*)(hi + idx) = make_uint4(hw[0], hw[1], hw[2], hw[3]);
    *(uint4*)(lo + idx) = make_uint4(lw[0], lw[1], lw[2], lw[3]);
}

// ============================================================================
// cp.async ping-pong GEMM core: C[128,128] = A[128,K] @ B[128,K]^T, bf16x3.
// 8 warps in 2(m) x 4(n); warp tile 64x32; acc[4][4][4]. (round-3 fragment
// geometry, proven; cp.async staging.)
// ============================================================================
#define ST2_AHI 0
#define ST2_ALO (128 * TPAD)       // 5120
#define ST2_BHI (2 * 128 * TPAD)   // 10240
#define ST2_BLO (3 * 128 * TPAD)   // 15360
#define ST2_SZ  (4 * 128 * TPAD)   // 20480 bf16 = 40960 B per stage
#define SMEM_DYN2 (2 * ST2_SZ * 2) // 81920 bytes

template<int KCH>
__device__ __forceinline__ void gemm_core_cp2(
    const __nv_bfloat16* __restrict__ Ahi, const __nv_bfloat16* __restrict__ Alo, int astr,
    const __nv_bfloat16* __restrict__ Bhi, const __nv_bfloat16* __restrict__ Blo, int bstr,
    float acc[4][4][4], __nv_bfloat16* sm)
{
    const int tid = threadIdx.x, wid = tid >> 5, lane = tid & 31;
    const int wm = (wid >> 2) * 64, wn = (wid & 3) * 32;
    const int arow = wm + (lane & 15), akc = (lane >> 4) * 8;
    const int brow = wn + (lane >> 4) * 8 + (lane & 7), bkc = ((lane >> 3) & 1) * 8;

    const int rT = tid >> 1, cT = (tid & 1) * 2;   // 128 rows x 4 16B-chunks/row

    auto issue = [&](int st, int k0) {
        __nv_bfloat16* base = sm + st * ST2_SZ;
#pragma unroll
        for (int j = 0; j < 2; j++) {
            int c = cT + j;
            CP16(smem_u32(base + ST2_AHI + rT * TPAD + c * 8), Ahi + (size_t)rT * astr + k0 + c * 8);
            CP16(smem_u32(base + ST2_ALO + rT * TPAD + c * 8), Alo + (size_t)rT * astr + k0 + c * 8);
            CP16(smem_u32(base + ST2_BHI + rT * TPAD + c * 8), Bhi + (size_t)rT * bstr + k0 + c * 8);
            CP16(smem_u32(base + ST2_BLO + rT * TPAD + c * 8), Blo + (size_t)rT * bstr + k0 + c * 8);
        }
        CP_COMMIT();
    };

    issue(0, 0);
    for (int ch = 0; ch < KCH; ch++) {
        if (ch + 1 < KCH) { issue((ch + 1) & 1, (ch + 1) * 32); CP_WAIT1(); }
        else              { CP_WAIT0(); }
        __syncthreads();

        const __nv_bfloat16* base = sm + (ch & 1) * ST2_SZ;
#pragma unroll
        for (int ks = 0; ks < 2; ks++) {
            const int kc = ks * 16;
            uint32_t ahi[4][4], alo[4][4];
#pragma unroll
            for (int mi = 0; mi < 4; mi++) {
                const int off = (arow + mi * 16) * TPAD + kc + akc;
                ldmx4(ahi[mi], base + ST2_AHI + off);
                ldmx4(alo[mi], base + ST2_ALO + off);
            }
            uint32_t bh[2][4], bl[2][4];
#pragma unroll
            for (int np = 0; np < 2; np++) {
                const int off = (brow + np * 16) * TPAD + kc + bkc;
                ldmx4(bh[np], base + ST2_BHI + off);
                ldmx4(bl[np], base + ST2_BLO + off);
            }
#pragma unroll
            for (int mi = 0; mi < 4; mi++)
#pragma unroll
                for (int nj = 0; nj < 4; nj++) {
                    const int np = nj >> 1, o = (nj & 1) * 2;
                    mma16816(acc[mi][nj], ahi[mi], bh[np][o], bh[np][o+1]);
                    mma16816(acc[mi][nj], ahi[mi], bl[np][o], bl[np][o+1]);
                    mma16816(acc[mi][nj], alo[mi], bh[np][o], bh[np][o+1]);
                }
        }
        __syncthreads();
    }
}

// ============================================================================
// Kernel -1: convert inputs to bf16 hi/lo (X, Wcat, rf)
// ============================================================================
#define NXE (BL * DLEN)        // 8388608
#define NWE (1024 * DLEN)      // 524288
#define NRE (MRF * MRF)        // 65536
#define CVT_BLOCKS ((NXE + NWE + NRE) / 8 / 256)

__global__ void k_cvt(const float* __restrict__ X,
                      const float* __restrict__ Wq, const float* __restrict__ Wk,
                      const float* __restrict__ Wv, const float* __restrict__ Wa,
                      const float* __restrict__ rf)
{
    size_t base = ((size_t)blockIdx.x * 256 + threadIdx.x) * 8;
    const float* src;
    __nv_bfloat16 *dhi, *dlo;
    if (base < NXE) {
        src = X + base; dhi = g_x_hi + base; dlo = g_x_lo + base;
    } else if (base < NXE + NWE) {
        size_t off = base - NXE;
        int sel = (int)(off >> 17);
        const float* W = (sel == 0) ? Wq : (sel == 1) ? Wk : (sel == 2) ? Wv : Wa;
        src = W + (off & 131071); dhi = g_w_hi + off; dlo = g_w_lo + off;
    } else {
        size_t off = base - NXE - NWE;
        src = rf + off; dhi = g_rf_hi + off; dlo = g_rf_lo + off;
    }
    float4 u = *(const float4*)src, v = *(const float4*)(src + 4);
    float xs[8] = {u.x, u.y, u.z, u.w, v.x, v.y, v.z, v.w};
    uint32_t hw[4], lw[4];
    cvt8(xs, hw, lw);
    *(uint4*)dhi = make_uint4(hw[0], hw[1], hw[2], hw[3]);
    *(uint4*)dlo = make_uint4(lw[0], lw[1], lw[2], lw[3]);
}

// ============================================================================
// Kernel 0: zero kv + ksum accumulators
// ============================================================================
__global__ void k_zero_acc()
{
    int idx = blockIdx.x * 256 + threadIdx.x;
    ((float4*)g_kv)[idx] = make_float4(0.f, 0.f, 0.f, 0.f);
    if (idx < NB * TWOM / 4)
        ((float4*)g_ksum)[idx] = make_float4(0.f, 0.f, 0.f, 0.f);
}

// ============================================================================
// Kernel 1: proj (128x128 tiles). bn 0..3 -> Q|K bf16 hi/lo; bn 4..7 -> V|Add.
// ============================================================================
__global__ void __launch_bounds__(256, 2) k_proj_mma()
{
    extern __shared__ __nv_bfloat16 sm[];
    const int bn = blockIdx.x;            // 0..7
    const int bm = blockIdx.y;            // 0..127

    const __nv_bfloat16* Ah = g_x_hi + (size_t)bm * 128 * DLEN;
    const __nv_bfloat16* Al = g_x_lo + (size_t)bm * 128 * DLEN;
    const __nv_bfloat16* Bh = g_w_hi + (size_t)bn * 128 * DLEN;
    const __nv_bfloat16* Bl = g_w_lo + (size_t)bn * 128 * DLEN;

    float acc[4][4][4] = {};
    gemm_core_cp2<16>(Ah, Al, DLEN, Bh, Bl, DLEN, acc, sm);

    const int tid = threadIdx.x, wid = tid >> 5, lane = tid & 31;
    const int r0 = bm * 128 + (wid >> 2) * 64 + (lane >> 2);
    const int c0 = bn * 128 + (wid & 3) * 32 + (lane & 3) * 2;

    if (bn < 4) {   // Q|K -> bf16 hi/lo, cols 0..511
#pragma unroll
        for (int mi = 0; mi < 4; mi++)
#pragma unroll
            for (int nj = 0; nj < 4; nj++) {
#pragma unroll
                for (int h = 0; h < 2; h++) {
                    int r = r0 + mi * 16 + h * 8, c = c0 + nj * 8;
                    float v0 = acc[mi][nj][h*2], v1 = acc[mi][nj][h*2+1];
                    __nv_bfloat16 h0 = __float2bfloat16_rn(v0);
                    __nv_bfloat16 h1 = __float2bfloat16_rn(v1);
                    __nv_bfloat16 l0 = __float2bfloat16_rn(v0 - __bfloat162float(h0));
                    __nv_bfloat16 l1 = __float2bfloat16_rn(v1 - __bfloat162float(h1));
                    size_t idx = (size_t)r * 512 + c;
                    *(uint32_t*)(g_qk_hi + idx) =
                        (uint32_t)__bfloat16_as_ushort(h0) | ((uint32_t)__bfloat16_as_ushort(h1) << 16);
                    *(uint32_t*)(g_qk_lo + idx) =
                        (uint32_t)__bfloat16_as_ushort(l0) | ((uint32_t)__bfloat16_as_ushort(l1) << 16);
                }
            }
    } else {        // V|Add -> fp32 qkva, cols 512..1023
#pragma unroll
        for (int mi = 0; mi < 4; mi++)
#pragma unroll
            for (int nj = 0; nj < 4; nj++) {
                int r = r0 + mi * 16, c = c0 + nj * 8;
                *(float2*)&g_qkva[(size_t)r * NPROJ + c]       = make_float2(acc[mi][nj][0], acc[mi][nj][1]);
                *(float2*)&g_qkva[(size_t)(r + 8) * NPROJ + c] = make_float2(acc[mi][nj][2], acc[mi][nj][3]);
            }
    }
}

// ============================================================================
// Kernel 2: rowscale from bf16 hi/lo Q|K
// ============================================================================
__global__ void k_rowscale()
{
    int warp = (blockIdx.x * blockDim.x + threadIdx.x) >> 5;
    int lane = threadIdx.x & 31;
    int isK = blockIdx.y;
    if (warp >= BL) return;
    const __nv_bfloat16* hi = g_qk_hi + (size_t)warp * 512 + (isK ? DM : 0);
    const __nv_bfloat16* lo = g_qk_lo + (size_t)warp * 512 + (isK ? DM : 0);
    float s = 0.f;
#pragma unroll
    for (int i = lane; i < DM; i += 32) {
        float v = __bfloat162float(hi[i]) + __bfloat162float(lo[i]);
        s = fmaf(v, v, s);
    }
#pragma unroll
    for (int o = 16; o; o >>= 1) s += __shfl_xor_sync(0xFFFFFFFFu, s, o);
    if (lane == 0) {
        float sc = expf(0.5f * s) * 0.0625f;
        (isK ? g_scale_k : g_scale_q)[warp] = sc;
    }
}

// ============================================================================
// Kernel 3: phi (128x128 tiles).  (Q|K)[128,256] @ rf[128,256]^T; sincos.
// ============================================================================
__global__ void __launch_bounds__(256, 2) k_phi_mma()
{
    extern __shared__ __nv_bfloat16 sm[];
    const int bn = blockIdx.x;            // 0..1
    const int bm = blockIdx.y;            // 0..127
    const int isK = blockIdx.z;

    const __nv_bfloat16* Ah = g_qk_hi + (size_t)bm * 128 * 512 + (isK ? DM : 0);
    const __nv_bfloat16* Al = g_qk_lo + (size_t)bm * 128 * 512 + (isK ? DM : 0);
    const __nv_bfloat16* Bh = g_rf_hi + (size_t)bn * 128 * MRF;
    const __nv_bfloat16* Bl = g_rf_lo + (size_t)bn * 128 * MRF;

    float acc[4][4][4] = {};
    gemm_core_cp2<8>(Ah, Al, 512, Bh, Bl, MRF, acc, sm);

    float* OUT = isK ? g_kp : g_qp;
    const float* SC = isK ? g_scale_k : g_scale_q;

    const int tid = threadIdx.x, wid = tid >> 5, lane = tid & 31;
    const int r0 = bm * 128 + (wid >> 2) * 64 + (lane >> 2);
    const int c0 = bn * 128 + (wid & 3) * 32 + (lane & 3) * 2;   // feature 0..255
#pragma unroll
    for (int mi = 0; mi < 4; mi++) {
        int r = r0 + mi * 16;
        float sa = SC[r], sb = SC[r + 8];
        float* rowa = OUT + (size_t)r * TWOM;
        float* rowb = OUT + (size_t)(r + 8) * TWOM;
#pragma unroll
        for (int nj = 0; nj < 4; nj++) {
            int c = c0 + nj * 8;
            float s0, cz0, s1, cz1, s2, cz2, s3, cz3;
            sincosf(TWO_PI * acc[mi][nj][0], &s0, &cz0);
            sincosf(TWO_PI * acc[mi][nj][1], &s1, &cz1);
            sincosf(TWO_PI * acc[mi][nj][2], &s2, &cz2);
            sincosf(TWO_PI * acc[mi][nj][3], &s3, &cz3);
            *(float2*)&rowa[c]      = make_float2(s0 * sa,  s1 * sa);
            *(float2*)&rowa[c + DM] = make_float2(cz0 * sa, cz1 * sa);
            *(float2*)&rowb[c]      = make_float2(s2 * sb,  s3 * sb);
            *(float2*)&rowb[c + DM] = make_float2(cz2 * sb, cz3 * sb);
        }
    }
}

// ============================================================================
// Kernel 4 (mma): kv[b, m, d] += sum_{l in split} kp[b,l,m] * v[b,l,d]
// (unchanged)
// ============================================================================
__global__ void __launch_bounds__(256, 2) k_kv_mma()
{
    __shared__ __nv_bfloat16 sAhi[32 * KTP],  sAlo[32 * KTP];
    __shared__ __nv_bfloat16 sBhi[32 * KTPB], sBlo[32 * KTPB];
    __shared__ float red[16][128];

    const int d0 = blockIdx.x * 64;
    const int m0 = blockIdx.y * 128;
    const int b  = blockIdx.z >> 2;
    const int sp = blockIdx.z & 3;
    const float* kpb = g_kp   + (size_t)b * LSEQ * TWOM  + m0;
    const float* vb  = g_qkva + (size_t)b * LSEQ * NPROJ + 2 * DM + d0;

    const int tid = threadIdx.x, wid = tid >> 5, lane = tid & 31;
    const int g8 = lane >> 3, r8 = lane & 7;
    const int wm = (wid >> 2) * 64, wn = (wid & 3) * 16;

    float acc[4][2][4] = {};
    float ksp[8] = {};

    const int arow0 = tid >> 4, acol8 = (tid & 15) * 8;
    const int brow0 = tid >> 3, bcol8 = (tid & 7) * 8;

    const int ch0 = sp * (LSEQ / 32 / LSPLIT);
    const int ch1 = ch0 + (LSEQ / 32 / LSPLIT);
    for (int ch = ch0; ch < ch1; ch++) {
        const int l0 = ch * 32;
#pragma unroll
        for (int i = 0; i < 2; i++) {
            int row = arow0 + i * 16;
            const float* p = kpb + (size_t)(l0 + row) * TWOM + acol8;
            float4 u = *(const float4*)p, v4 = *(const float4*)(p + 4);
            float xs[8] = {u.x, u.y, u.z, u.w, v4.x, v4.y, v4.z, v4.w};
            uint32_t hw[4], lw[4];
            cvt8(xs, hw, lw);
#pragma unroll
            for (int q = 0; q < 8; q++) ksp[q] += xs[q];
            *(uint4*)(sAhi + row * KTP + acol8) = make_uint4(hw[0], hw[1], hw[2], hw[3]);
            *(uint4*)(sAlo + row * KTP + acol8) = make_uint4(lw[0], lw[1], lw[2], lw[3]);
        }
        stage8_cvt(vb + (size_t)(l0 + brow0) * NPROJ + bcol8, sBhi, sBlo, brow0 * KTPB + bcol8);
        __syncthreads();

#pragma unroll
        for (int ks = 0; ks < 2; ks++) {
            const int kc = ks * 16;
            uint32_t ahi[4][4], alo[4][4];
#pragma unroll
            for (int mi = 0; mi < 4; mi++) {
                const int off = (kc + r8 + (g8 >> 1) * 8) * KTP + wm + mi * 16 + (g8 & 1) * 8;
                ldmx4t(ahi[mi], sAhi + off);
                ldmx4t(alo[mi], sAlo + off);
            }
            uint32_t bhi[4], blo[4];
            {
                const int off = (kc + r8 + (g8 & 1) * 8) * KTPB + wn + (g8 >> 1) * 8;
                ldmx4t(bhi, sBhi + off);
                ldmx4t(blo, sBlo + off);
            }
#pragma unroll
            for (int mi = 0; mi < 4; mi++)
#pragma unroll
                for (int nj = 0; nj < 2; nj++) {
                    const int o = nj * 2;
                    mma16816(acc[mi][nj], ahi[mi], bhi[o], bhi[o+1]);
                    mma16816(acc[mi][nj], ahi[mi], blo[o], blo[o+1]);
                    mma16816(acc[mi][nj], alo[mi], bhi[o], bhi[o+1]);
                }
        }
        __syncthreads();
    }

    const int rr0 = m0 + wm + (lane >> 2);
    const int cc0 = d0 + wn + (lane & 3) * 2;
#pragma unroll
    for (int mi = 0; mi < 4; mi++)
#pragma unroll
        for (int nj = 0; nj < 2; nj++) {
            int r = rr0 + mi * 16, c = cc0 + nj * 8;
            float* p0 = &g_kv[((size_t)b * TWOM + r) * DM + c];
            float* p1 = &g_kv[((size_t)b * TWOM + r + 8) * DM + c];
            atomicAdd(p0,     acc[mi][nj][0]);
            atomicAdd(p0 + 1, acc[mi][nj][1]);
            atomicAdd(p1,     acc[mi][nj][2]);
            atomicAdd(p1 + 1, acc[mi][nj][3]);
        }

    if (blockIdx.x == 0) {
#pragma unroll
        for (int q = 0; q < 8; q++) red[arow0][acol8 + q] = ksp[q];
        __syncthreads();
        if (tid < 128) {
            float s = 0.f;
#pragma unroll
            for (int j = 0; j < 16; j++) s += red[j][tid];
            atomicAdd(&g_ksum[b * TWOM + m0 + tid], s);
        }
    }
}

// ============================================================================
// Kernel 5 (mma): num + fused denom + epilogue   (unchanged)
// ============================================================================
__global__ void __launch_bounds__(256, 2) k_num_mma(const float* __restrict__ b_add)
{
    __shared__ __nv_bfloat16 sAhi[128 * TPAD], sAlo[128 * TPAD];
    __shared__ __nv_bfloat16 sBhi[32 * KTPB],  sBlo[32 * KTPB];
    __shared__ float red2[128][4];

    const int d0 = blockIdx.x * 64;
    const int lt = blockIdx.y * 128;
    const int b  = blockIdx.z;
    const float* qpb = g_qp + (size_t)(b * LSEQ + lt) * TWOM;
    const float* kvb = g_kv + (size_t)b * TWOM * DM + d0;
    const float* ksb = g_ksum + b * TWOM;

    const int tid = threadIdx.x, wid = tid >> 5, lane = tid & 31;
    const int g8 = lane >> 3, r8 = lane & 7;
    const int wm = (wid >> 2) * 64, wn = (wid & 3) * 16;
    const int arow = wm + (lane & 15);
    const int akc  = (lane >> 4) * 8;

    float acc[4][2][4] = {};
    float dn[2] = {0.f, 0.f};

    const int srow0 = tid >> 2, scol8 = (tid & 3) * 8;
    const int brow0 = tid >> 3, bcol8 = (tid & 7) * 8;

    float pa[2][8], pb[8];
#pragma unroll
    for (int i = 0; i < 2; i++) {
        const float* p = qpb + (size_t)(srow0 + i * 64) * TWOM + scol8;
        *(float4*)&pa[i][0] = *(const float4*)p;
        *(float4*)&pa[i][4] = *(const float4*)(p + 4);
    }
    {
        const float* q = kvb + (size_t)brow0 * DM + bcol8;
        *(float4*)&pb[0] = *(const float4*)q;
        *(float4*)&pb[4] = *(const float4*)(q + 4);
    }

    for (int ch = 0; ch < TWOM / 32; ch++) {
        const int k0 = ch * 32;
#pragma unroll
        for (int i = 0; i < 2; i++) {
            int row = srow0 + i * 64;
            uint32_t hw[4], lw[4];
            cvt8(pa[i], hw, lw);
            const float* ks = ksb + k0 + scol8;
#pragma unroll
            for (int q = 0; q < 8; q++) dn[i] = fmaf(pa[i][q], ks[q], dn[i]);
            *(uint4*)(sAhi + row * TPAD + scol8) = make_uint4(hw[0], hw[1], hw[2], hw[3]);
            *(uint4*)(sAlo + row * TPAD + scol8) = make_uint4(lw[0], lw[1], lw[2], lw[3]);
        }
        {
            uint32_t hw[4], lw[4];
            cvt8(pb, hw, lw);
            int idx = brow0 * KTPB + bcol8;
            *(uint4*)(sBhi + idx) = make_uint4(hw[0], hw[1], hw[2], hw[3]);
            *(uint4*)(sBlo + idx) = make_uint4(lw[0], lw[1], lw[2], lw[3]);
        }
        __syncthreads();

        if (ch + 1 < TWOM / 32) {
            const int k1 = (ch + 1) * 32;
#pragma unroll
            for (int i = 0; i < 2; i++) {
                const float* p = qpb + (size_t)(srow0 + i * 64) * TWOM + k1 + scol8;
                *(float4*)&pa[i][0] = *(const float4*)p;
                *(float4*)&pa[i][4] = *(const float4*)(p + 4);
            }
            const float* q = kvb + (size_t)(k1 + brow0) * DM + bcol8;
            *(float4*)&pb[0] = *(const float4*)q;
            *(float4*)&pb[4] = *(const float4*)(q + 4);
        }

#pragma unroll
        for (int ks2 = 0; ks2 < 2; ks2++) {
            const int kc = ks2 * 16;
            uint32_t ahi[4][4], alo[4][4];
#pragma unroll
            for (int mi = 0; mi < 4; mi++) {
                const int off = (arow + mi * 16) * TPAD + kc + akc;
                ldmx4(ahi[mi], sAhi + off);
                ldmx4(alo[mi], sAlo + off);
            }
            uint32_t bhi[4], blo[4];
            {
                const int off = (kc + r8 + (g8 & 1) * 8) * KTPB + wn + (g8 >> 1) * 8;
                ldmx4t(bhi, sBhi + off);
                ldmx4t(blo, sBlo + off);
            }
#pragma unroll
            for (int mi = 0; mi < 4; mi++)
#pragma unroll
                for (int nj = 0; nj < 2; nj++) {
                    const int o = nj * 2;
                    mma16816(acc[mi][nj], ahi[mi], bhi[o], bhi[o+1]);
                    mma16816(acc[mi][nj], ahi[mi], blo[o], blo[o+1]);
                    mma16816(acc[mi][nj], alo[mi], bhi[o], bhi[o+1]);
                }
        }
        __syncthreads();
    }

    red2[srow0][tid & 3]      = dn[0];
    red2[srow0 + 64][tid & 3] = dn[1];
    __syncthreads();

    const int rr0 = wm + (lane >> 2);
    const int cc0 = d0 + wn + (lane & 3) * 2;
#pragma unroll
    for (int mi = 0; mi < 4; mi++) {
#pragma unroll
        for (int h = 0; h < 2; h++) {
            int rloc = rr0 + mi * 16 + h * 8;
            float den = red2[rloc][0] + red2[rloc][1] + red2[rloc][2] + red2[rloc][3];
            float inv = 1.0f / den;
            int rg = b * LSEQ + lt + rloc;
            const float* addp = g_qkva + (size_t)rg * NPROJ + 3 * DM;
            float* orow = g_out + (size_t)rg * DM;
#pragma unroll
            for (int nj = 0; nj < 2; nj++) {
                int c = cc0 + nj * 8;
                float v0 = acc[mi][nj][h*2]   * inv + addp[c]     + b_add[c];
                float v1 = acc[mi][nj][h*2+1] * inv + addp[c + 1] + b_add[c + 1];
                *(float2*)&orow[c] = make_float2(v0, v1);
            }
        }
    }
}

// ============================================================================
// Kernel 6a: init d_out with b_final.
// ============================================================================
__global__ void k_init_out(float* __restrict__ out, const float* __restrict__ bf)
{
    int i = threadIdx.x;
    out[i] = bf[i & 63];
}

// ============================================================================
// Kernel 6b: final GEMM (split-K atomics)
// ============================================================================
__global__ void __launch_bounds__(256) k_final(const float* __restrict__ Wf,
                                               float* __restrict__ out)
{
    __shared__ float Ws[64][130];
    __shared__ float Os[8][132];

    const int tid = threadIdx.x;
    const int c  = tid & 63;
    const int bb = tid >> 6;
    float acc0 = 0.f, acc1 = 0.f;
    const int f0 = blockIdx.x * 1024;

    for (int t = 0; t < 1024; t += 128) {
        const int fbase = f0 + t;
#pragma unroll
        for (int i = 0; i < 8; i++) {
            int v = tid + i * 256;
            int cc = v >> 5, f4 = (v & 31) * 4;
            float4 w = *(const float4*)(Wf + (size_t)cc * FTOT + fbase + f4);
            Ws[cc][f4] = w.x; Ws[cc][f4+1] = w.y; Ws[cc][f4+2] = w.z; Ws[cc][f4+3] = w.w;
        }
        {
            int v = tid;
            int bo = v >> 5, f4 = (v & 31) * 4;
            float4 o = *(const float4*)(g_out + (size_t)bo * FTOT + fbase + f4);
            Os[bo][f4] = o.x; Os[bo][f4+1] = o.y; Os[bo][f4+2] = o.z; Os[bo][f4+3] = o.w;
        }
        __syncthreads();
#pragma unroll 8
        for (int fi = 0; fi < 128; fi++) {
            float w = Ws[c][fi];
            acc0 = fmaf(Os[bb][fi],     w, acc0);
            acc1 = fmaf(Os[bb + 4][fi], w, acc1);
        }
        __syncthreads();
    }
    atomicAdd(&out[bb * NCLASS + c],       acc0);
    atomicAdd(&out[(bb + 4) * NCLASS + c], acc1);
}

// ============================================================================
extern "C" void kernel_launch(void* const* d_in, const int* in_sizes, int n_in,
                              void* d_out, int out_size)
{
    const float* X  = (const float*)d_in[0];
    // d_in[1..6]: unused scalars
    const float* Wq = (const float*)d_in[7];
    const float* Wk = (const float*)d_in[8];
    const float* Wv = (const float*)d_in[9];
    const float* Wa = (const float*)d_in[10];
    const float* bA = (const float*)d_in[11];
    const float* Wf = (const float*)d_in[12];
    const float* bF = (const float*)d_in[13];
    const float* rf = (const float*)d_in[14];
    float* out = (float*)d_out;

    static bool attr_done = false;
    if (!attr_done) {
        cudaFuncSetAttribute(k_proj_mma, cudaFuncAttributeMaxDynamicSharedMemorySize, SMEM_DYN2);
        cudaFuncSetAttribute(k_phi_mma,  cudaFuncAttributeMaxDynamicSharedMemorySize, SMEM_DYN2);
        attr_done = true;
    }

    k_zero_acc<<<1024,            256>>>();
    k_cvt     <<<CVT_BLOCKS,      256>>>(X, Wq, Wk, Wv, Wa, rf);
    k_proj_mma<<<dim3(8, 128),    256, SMEM_DYN2>>>();
    k_rowscale<<<dim3(2048, 2),   256>>>();
    k_phi_mma <<<dim3(2, 128, 2), 256, SMEM_DYN2>>>();
    k_kv_mma  <<<dim3(4, 4, 8 * LSPLIT), 256>>>();
    k_num_mma <<<dim3(4, 16, 8),  256>>>(bA);
    k_init_out<<<1, 512>>>(out, bF);
    k_final   <<<512, 256>>>(Wf, out);
}